// round 11
// baseline (speedup 1.0000x reference)
#include <cuda_runtime.h>
#include <math.h>
#include <stdint.h>

// ---------------------------------------------------------------------------
// Problem constants (x: [8192, 512] fp32)
// ---------------------------------------------------------------------------
constexpr int NROW = 8192;
constexpr int DIM  = 512;

constexpr int BM   = 128;           // rows per strip
constexpr int BN   = 128;           // cols per tile
constexpr int KCB  = 128;           // K per smem chunk (128 int8 = 128B rows)
constexpr int KCH  = DIM / KCB;     // 4 K-chunks per tile
constexpr int NSTRIP = NROW / BM;   // 64 strips
constexpr int CHB  = BM * KCB;      // 16384 B per chunk tile
constexpr int NTILES = 33 * 32 + 32 * 32;   // 2080
constexpr int NCTA   = 148;         // == SM count -> co-resident guaranteed

constexpr int SMO_A = 0;                       // 4 * 16KB resident A strip
constexpr int SMO_B = SMO_A + KCH * CHB;       // 4-slot B ring
constexpr int SMEM_SZ = SMO_B + 4 * CHB;       // 131072 B

// Scratch (no allocations allowed anywhere)
__device__ uint8_t g_xq[NROW * DIM];           // int8 quantized x
__device__ float   g_scale[NROW];              // per-row dequant scale
__device__ unsigned long long g_pack[NROW];    // packed (valkey<<32)|(0x7FFFFFFF-idx)
__device__ float g_term[NROW];
__device__ unsigned g_bar_count;               // self-resetting per barrier
__device__ unsigned g_bar_gen;                 // monotonic (replay-safe)

// ---------------------------------------------------------------------------
// PTX helpers (compute_100-safe)
// ---------------------------------------------------------------------------
__device__ __forceinline__ uint32_t smem_u32(const void* p) {
    uint32_t a;
    asm("{ .reg .u64 t; cvta.to.shared.u64 t, %1; cvt.u32.u64 %0, t; }"
        : "=r"(a) : "l"(p));
    return a;
}
__device__ __forceinline__ void cp16(uint32_t s, const void* g) {
    asm volatile("cp.async.cg.shared.global [%0], [%1], 16;" :: "r"(s), "l"(g));
}
#define CP_COMMIT() asm volatile("cp.async.commit_group;" ::: "memory")
#define CP_WAIT(n)  asm volatile("cp.async.wait_group %0;" :: "n"(n) : "memory")

__device__ __forceinline__ uint32_t sw128(uint32_t off) {
    return off ^ ((off >> 3) & 0x70);
}
__device__ __forceinline__ void ldsm4(uint32_t* r, uint32_t addr) {
    asm volatile("ldmatrix.sync.aligned.m8n8.x4.shared.b16 {%0,%1,%2,%3}, [%4];"
                 : "=r"(r[0]), "=r"(r[1]), "=r"(r[2]), "=r"(r[3]) : "r"(addr));
}
__device__ __forceinline__ void mma16832s8(int* d, const uint32_t* a, const uint32_t* b) {
    asm volatile(
        "mma.sync.aligned.m16n8k32.row.col.s32.s8.s8.s32 "
        "{%0,%1,%2,%3}, {%4,%5,%6,%7}, {%8,%9}, {%0,%1,%2,%3};"
        : "+r"(d[0]), "+r"(d[1]), "+r"(d[2]), "+r"(d[3])
        : "r"(a[0]), "r"(a[1]), "r"(a[2]), "r"(a[3]), "r"(b[0]), "r"(b[1]));
}

// saturating s8 pack: d = q0 | q1<<8 | q2<<16 | q3<<24
__device__ __forceinline__ uint32_t pack4s8(int q0, int q1, int q2, int q3) {
    uint32_t t, d;
    asm("cvt.pack.sat.s8.s32.b32 %0, %1, %2, %3;" : "=r"(t) : "r"(q3), "r"(q2), "r"(0));
    asm("cvt.pack.sat.s8.s32.b32 %0, %1, %2, %3;" : "=r"(d) : "r"(q1), "r"(q0), "r"(t));
    return d;
}

// Monotone packed argmax key: larger value -> larger pack; equal value ->
// smaller index -> larger pack (first-index tie-break).
__device__ __forceinline__ void atom_pack_max(unsigned long long* p, float v, int idx) {
    const uint32_t b = __float_as_uint(v);
    const uint32_t key = (b & 0x80000000u) ? ~b : (b | 0x80000000u);
    const unsigned long long pk =
        ((unsigned long long)key << 32) | (uint32_t)(0x7FFFFFFFu - idx);
    atomicMax(p, pk);
}

// strip-major flattened tile list helpers
__device__ __forceinline__ void strip_of(int t, int& i, int& d) {
    if (t < 33 * 32) { i = t / 33; d = t - i * 33; }
    else { const int u = t - 33 * 32; i = 32 + u / 32; d = u & 31; }
}
__device__ __forceinline__ int strip_end(int i) {
    return (i < 32) ? (i + 1) * 33 : 33 * 32 + (i - 31) * 32;
}

// Sense-reversing grid barrier. count self-resets; gen monotonic so the
// pattern is safe across CUDA-graph replays. All NCTA CTAs are co-resident
// (grid == SM count, 1 CTA/SM at this smem footprint).
__device__ __forceinline__ void grid_barrier(int tid) {
    __syncthreads();
    if (tid == 0) {
        __threadfence();
        const unsigned gen = atomicAdd(&g_bar_gen, 0u);
        const unsigned arrived = atomicAdd(&g_bar_count, 1u);
        if (arrived == NCTA - 1) {
            g_bar_count = 0;
            __threadfence();
            atomicAdd(&g_bar_gen, 1u);
        } else {
            while (atomicAdd(&g_bar_gen, 0u) == gen) __nanosleep(64);
        }
        __threadfence();
    }
    __syncthreads();
}

// ---------------------------------------------------------------------------
// Persistent fused kernel: quant -> barrier -> gemm+argmax -> barrier ->
// rho -> barrier -> loss (CTA 0). 148 CTAs x 256 threads.
// ---------------------------------------------------------------------------
__global__ __launch_bounds__(256, 1) void fused_kernel(const float* __restrict__ x,
                                                       float* __restrict__ out) {
    extern __shared__ __align__(128) char smem[];
    const uint32_t sb = smem_u32(smem);

    const int tid  = threadIdx.x;
    const int wid  = tid >> 5;
    const int lane = tid & 31;
    const int bid  = blockIdx.x;

    // =================== Phase 1: int8 quantization =======================
    // Row-groups of 8 (one row per warp), strided across CTAs.
    for (int grp = bid; grp < NROW / 8; grp += NCTA) {
        const int row = grp * 8 + wid;

        const float4* rp = reinterpret_cast<const float4*>(x + (size_t)row * DIM) + lane * 4;
        float4 v[4];
#pragma unroll
        for (int q = 0; q < 4; ++q) v[q] = rp[q];

        uint32_t mb = 0;
#pragma unroll
        for (int q = 0; q < 4; ++q) {
            mb = max(mb, __float_as_uint(fabsf(v[q].x)));
            mb = max(mb, __float_as_uint(fabsf(v[q].y)));
            mb = max(mb, __float_as_uint(fabsf(v[q].z)));
            mb = max(mb, __float_as_uint(fabsf(v[q].w)));
        }
        const float m   = __uint_as_float(__reduce_max_sync(0xffffffffu, mb));
        const float inv = 127.0f / m;

        uint4 o4;
        uint32_t* op = &o4.x;
#pragma unroll
        for (int q = 0; q < 4; ++q)
            op[q] = pack4s8(__float2int_rn(v[q].x * inv), __float2int_rn(v[q].y * inv),
                            __float2int_rn(v[q].z * inv), __float2int_rn(v[q].w * inv));
        reinterpret_cast<uint4*>(g_xq)[row * (DIM / 16) + lane] = o4;

        if (lane == 0) {
            g_scale[row] = m * (1.0f / 127.0f);
            g_pack[row]  = 0ull;     // key=0 < any real key
        }
    }

    grid_barrier(tid);

    // =================== Phase 2: gemm + dual-sided argmax ================
    {
        const int wr = wid >> 2;            // warp row (0-1) -> 64 rows
        const int wc = wid & 3;             // warp col (0-3) -> 32 cols

        const int t_begin = (int)((long long)bid * NTILES / NCTA);
        const int t_end   = (int)((long long)(bid + 1) * NTILES / NCTA);

        const uint8_t* xq = g_xq;

        const int a_row_lo = ((lane >> 3) & 1) * 8 + (lane & 7);
        const int a_kext   = (lane >> 4) * 16;
        const int b_row_lo = ((lane >> 4) & 1) * 8 + (lane & 7);
        const int b_kext   = ((lane >> 3) & 1) * 16;

        float* sV = reinterpret_cast<float*>(smem + SMO_B);      // scratch [128][4]
        int*   sI = reinterpret_cast<int*>(smem + SMO_B + 2048);

        int t = t_begin;
        while (t < t_end) {
            int strip, d0;
            strip_of(t, strip, d0);
            const int seg_end = min(t_end, strip_end(strip));
            const int NC   = (seg_end - t) * KCH;
            const int m0   = strip * BM;

            // per-segment row scales (candidate factor for the column fold)
            float srow[8];
#pragma unroll
            for (int mt = 0; mt < 4; ++mt) {
                const int r0 = m0 + wr * 64 + mt * 16 + (lane >> 2);
                srow[mt * 2]     = g_scale[r0];
                srow[mt * 2 + 1] = g_scale[r0 + 8];
            }

            __syncthreads();   // prior segment fully consumed A & B & scratch

            // ---- A strip: 4 chunks of [128 x 128] int8, SW128 (one group)
#pragma unroll
            for (int kc = 0; kc < KCH; ++kc) {
#pragma unroll
                for (int i = 0; i < 4; ++i) {
                    const int u   = i * 256 + tid;       // 16B units
                    const int row = u >> 3;
                    const int c16 = u & 7;
                    cp16(sb + SMO_A + kc * CHB + sw128(row * 128 + c16 * 16),
                         xq + (size_t)(m0 + row) * DIM + kc * KCB + c16 * 16);
                }
            }
            CP_COMMIT();

            // ---- B prologue: chunks 0..2 into slots 0..2
#pragma unroll
            for (int p = 0; p < 3; ++p) {
                const int j  = (strip + d0) & (NSTRIP - 1);  // p<4 -> tile 0
                const int kc = p;
                const int n0 = j * BN;
#pragma unroll
                for (int i = 0; i < 4; ++i) {
                    const int u   = i * 256 + tid;
                    const int row = u >> 3;
                    const int c16 = u & 7;
                    cp16(sb + SMO_B + p * CHB + sw128(row * 128 + c16 * 16),
                         xq + (size_t)(n0 + row) * DIM + kc * KCB + c16 * 16);
                }
                CP_COMMIT();
            }
            CP_WAIT(3);          // A landed
            __syncthreads();

            int acc[4][4][4];
#pragma unroll
            for (int mt = 0; mt < 4; ++mt)
#pragma unroll
                for (int nt = 0; nt < 4; ++nt)
#pragma unroll
                    for (int k = 0; k < 4; ++k) acc[mt][nt][k] = 0;

            float bestV[8];
            int   bestI[8];
#pragma unroll
            for (int i = 0; i < 8; ++i) { bestV[i] = -3.402823466e38f; bestI[i] = 0; }

            for (int g = 0; g < NC; ++g) {
                CP_WAIT(2);
                __syncthreads();

                const int gn = g + 3;
                if (gn < NC) {
                    const int j  = (strip + d0 + (gn >> 2)) & (NSTRIP - 1);
                    const int kc = gn & 3;
                    const int n0 = j * BN;
                    const uint32_t dst = sb + SMO_B + (gn & 3) * CHB;
#pragma unroll
                    for (int i = 0; i < 4; ++i) {
                        const int u   = i * 256 + tid;
                        const int row = u >> 3;
                        const int c16 = u & 7;
                        cp16(dst + sw128(row * 128 + c16 * 16),
                             xq + (size_t)(n0 + row) * DIM + kc * KCB + c16 * 16);
                    }
                }
                CP_COMMIT();

                // ---- compute chunk g: batch ALL fragments, then 64 mma
                const uint32_t abase = sb + SMO_A + (g & 3) * CHB;
                const uint32_t bbase = sb + SMO_B + (g & 3) * CHB;
                uint32_t afr[4][4][4];    // [ks][mt][4]
                uint32_t bfr[4][2][4];    // [ks][h][4]
#pragma unroll
                for (int ks = 0; ks < 4; ++ks) {
#pragma unroll
                    for (int mt = 0; mt < 4; ++mt) {
                        const int row = wr * 64 + mt * 16 + a_row_lo;
                        ldsm4(afr[ks][mt], abase + sw128(row * 128 + ks * 32 + a_kext));
                    }
#pragma unroll
                    for (int h2 = 0; h2 < 2; ++h2) {
                        const int row = wc * 32 + h2 * 16 + b_row_lo;
                        ldsm4(bfr[ks][h2], bbase + sw128(row * 128 + ks * 32 + b_kext));
                    }
                }
#pragma unroll
                for (int ks = 0; ks < 4; ++ks)
#pragma unroll
                    for (int mt = 0; mt < 4; ++mt)
#pragma unroll
                        for (int nt = 0; nt < 4; ++nt)
                            mma16832s8(acc[mt][nt], afr[ks][mt],
                                       &bfr[ks][nt >> 1][(nt & 1) * 2]);

                // ---- tile finished (K=512): dual-sided fold, reset acc
                if ((g & 3) == 3) {
                    const int d    = d0 + (g >> 2);
                    const int j    = (strip + d) & (NSTRIP - 1);
                    const int nc0  = j * BN + wc * 32;
                    const bool diag = (d == 0);

                    float scs[8];
#pragma unroll
                    for (int nt = 0; nt < 4; ++nt) {
                        const int c0 = nc0 + nt * 8 + (lane & 3) * 2;
                        scs[nt * 2]     = g_scale[c0];
                        scs[nt * 2 + 1] = g_scale[c0 + 1];
                    }

                    // row side: v = s_col * dot (missing s_row constant/slot)
#pragma unroll
                    for (int mt = 0; mt < 4; ++mt) {
                        const int row0 = m0 + wr * 64 + mt * 16 + (lane >> 2);
                        const int row1 = row0 + 8;
#pragma unroll
                        for (int nt = 0; nt < 4; ++nt) {
                            const int c0 = nc0 + nt * 8 + (lane & 3) * 2;
                            const float v00 = (float)acc[mt][nt][0] * scs[nt * 2];
                            const float v01 = (float)acc[mt][nt][1] * scs[nt * 2 + 1];
                            const float v10 = (float)acc[mt][nt][2] * scs[nt * 2];
                            const float v11 = (float)acc[mt][nt][3] * scs[nt * 2 + 1];
                            const int b0 = mt * 2, b1 = mt * 2 + 1;
                            if (c0 != row0 && v00 > bestV[b0]) { bestV[b0] = v00; bestI[b0] = c0; }
                            if (c0 + 1 != row0 && v01 > bestV[b0]) { bestV[b0] = v01; bestI[b0] = c0 + 1; }
                            if (c0 != row1 && v10 > bestV[b1]) { bestV[b1] = v10; bestI[b1] = c0; }
                            if (c0 + 1 != row1 && v11 > bestV[b1]) { bestV[b1] = v11; bestI[b1] = c0 + 1; }
                        }
                    }

                    // column side: v = s_row * dot, skipped for diagonal
                    if (!diag) {
                        float cV[8];
                        int   cI[8];
#pragma unroll
                        for (int k = 0; k < 8; ++k) { cV[k] = -3.402823466e38f; cI[k] = 0; }
#pragma unroll
                        for (int mt = 0; mt < 4; ++mt) {
                            const int row0 = m0 + wr * 64 + mt * 16 + (lane >> 2);
                            const int row1 = row0 + 8;
                            const float s0 = srow[mt * 2], s1 = srow[mt * 2 + 1];
#pragma unroll
                            for (int nt = 0; nt < 4; ++nt) {
                                const int k0 = nt * 2, k1 = nt * 2 + 1;
                                const float v00 = (float)acc[mt][nt][0] * s0;
                                const float v01 = (float)acc[mt][nt][1] * s0;
                                const float v10 = (float)acc[mt][nt][2] * s1;
                                const float v11 = (float)acc[mt][nt][3] * s1;
                                if (v00 > cV[k0]) { cV[k0] = v00; cI[k0] = row0; }
                                if (v10 > cV[k0]) { cV[k0] = v10; cI[k0] = row1; }
                                if (v01 > cV[k1]) { cV[k1] = v01; cI[k1] = row0; }
                                if (v11 > cV[k1]) { cV[k1] = v11; cI[k1] = row1; }
                            }
                        }
#pragma unroll
                        for (int k = 0; k < 8; ++k) {
                            float v = cV[k];
                            int   ci = cI[k];
#pragma unroll
                            for (int o = 4; o <= 16; o <<= 1) {
                                const float ov = __shfl_xor_sync(0xffffffffu, v, o);
                                const int   oi = __shfl_xor_sync(0xffffffffu, ci, o);
                                if (ov > v || (ov == v && oi < ci)) { v = ov; ci = oi; }
                            }
                            if ((lane >> 2) == 0) {
                                const int col = nc0 + (k >> 1) * 8 + (lane & 3) * 2 + (k & 1);
                                atom_pack_max(&g_pack[col], v, ci);
                            }
                        }
                    }

#pragma unroll
                    for (int mt = 0; mt < 4; ++mt)
#pragma unroll
                        for (int nt = 0; nt < 4; ++nt) {
                            acc[mt][nt][0] = 0; acc[mt][nt][1] = 0;
                            acc[mt][nt][2] = 0; acc[mt][nt][3] = 0;
                        }
                }
            }

            // ---- flush row-side bests for this strip segment
            __syncthreads();   // ring quiescent -> reuse as scratch
#pragma unroll
            for (int b = 0; b < 8; ++b) {
                float v = bestV[b];
                int   i = bestI[b];
#pragma unroll
                for (int o = 2; o > 0; o >>= 1) {
                    const float ov = __shfl_xor_sync(0xffffffffu, v, o);
                    const int   oi = __shfl_xor_sync(0xffffffffu, i, o);
                    if (ov > v || (ov == v && oi < i)) { v = ov; i = oi; }
                }
                if ((lane & 3) == 0) {
                    const int lrow = wr * 64 + (b >> 1) * 16 + (b & 1) * 8 + (lane >> 2);
                    sV[lrow * 4 + wc] = v;
                    sI[lrow * 4 + wc] = i;
                }
            }
            __syncthreads();
            if (tid < BM) {
                float v = sV[tid * 4];
                int   i = sI[tid * 4];
#pragma unroll
                for (int q = 1; q < 4; ++q) {
                    const float ov = sV[tid * 4 + q];
                    const int   oi = sI[tid * 4 + q];
                    if (ov > v || (ov == v && oi < i)) { v = ov; i = oi; }
                }
                atom_pack_max(&g_pack[m0 + tid], v, i);
            }

            t = seg_end;
        }
    }

    grid_barrier(tid);

    // =================== Phase 3: rho (exact fp32) ========================
    for (int grp = bid; grp < NROW / 8; grp += NCTA) {
        const int row = grp * 8 + wid;

        const unsigned long long p = g_pack[row];
        const int nn = 0x7FFFFFFF - (int)(uint32_t)(p & 0xFFFFFFFFull);

        const float4* ra = reinterpret_cast<const float4*>(x + (size_t)row * DIM);
        const float4* rb = reinterpret_cast<const float4*>(x + (size_t)nn  * DIM);
        float s = 0.0f;
#pragma unroll
        for (int q = 0; q < 4; ++q) {
            const float4 a = ra[lane + 32 * q];
            const float4 b = rb[lane + 32 * q];
            const float dx = a.x - b.x + 1e-6f;
            const float dy = a.y - b.y + 1e-6f;
            const float dz = a.z - b.z + 1e-6f;
            const float dw = a.w - b.w + 1e-6f;
            s += dx * dx + dy * dy + dz * dz + dw * dw;
        }
#pragma unroll
        for (int o = 16; o > 0; o >>= 1) s += __shfl_xor_sync(0xffffffffu, s, o);

        if (lane == 0) g_term[row] = logf(sqrtf(s) + 1e-8f);
    }

    grid_barrier(tid);

    // =================== Phase 4: loss (CTA 0, fixed order) ===============
    if (bid == 0) {
        __shared__ float ws[8];
        float acc = 0.0f;
        for (int i = tid; i < NROW; i += 256) acc += g_term[i];
#pragma unroll
        for (int o = 16; o > 0; o >>= 1) acc += __shfl_xor_sync(0xffffffffu, acc, o);
        if (lane == 0) ws[wid] = acc;
        __syncthreads();
        if (tid == 0) {
            float tot = 0.0f;
#pragma unroll
            for (int w = 0; w < 8; ++w) tot += ws[w];
            out[0] = -tot / (float)NROW;
        }
    }
}

extern "C" void kernel_launch(void* const* d_in, const int* in_sizes, int n_in,
                              void* d_out, int out_size) {
    (void)in_sizes; (void)n_in; (void)out_size;
    const float* x = (const float*)d_in[0];
    float* out = (float*)d_out;

    cudaFuncSetAttribute(fused_kernel,
                         cudaFuncAttributeMaxDynamicSharedMemorySize, SMEM_SZ);

    fused_kernel<<<NCTA, 256, SMEM_SZ>>>(x, out);
}

// round 12
// speedup vs baseline: 1.0901x; 1.0901x over previous
#include <cuda_runtime.h>
#include <math.h>
#include <stdint.h>

// ---------------------------------------------------------------------------
// Problem constants (x: [8192, 512] fp32)
// ---------------------------------------------------------------------------
constexpr int NROW = 8192;
constexpr int DIM  = 512;

constexpr int BM   = 128;           // rows per strip
constexpr int BN   = 128;           // cols per tile
constexpr int KCB  = 128;           // K per smem chunk (128 int8 = 128B rows)
constexpr int KCH  = DIM / KCB;     // 4 K-chunks per tile
constexpr int NSTRIP = NROW / BM;   // 64 strips
constexpr int CHB  = BM * KCB;      // 16384 B per chunk tile
constexpr int NTILES = 33 * 32 + 32 * 32;   // 2080
constexpr int NCTA   = 148;

constexpr int SMO_A = 0;                       // 4 * 16KB resident A strip
constexpr int SMO_B = SMO_A + KCH * CHB;       // 4-slot B ring
constexpr int SMEM_SZ = SMO_B + 4 * CHB;       // 131072 B

// Scratch (no allocations allowed anywhere)
__device__ uint8_t g_xq[NROW * DIM];           // int8 quantized x
__device__ float   g_scale[NROW];              // per-row dequant scale
__device__ unsigned long long g_pack[NROW];    // packed (valkey<<32)|(0x7FFFFFFF-idx)
__device__ float g_term[NROW];
__device__ int   g_cnt;

// ---------------------------------------------------------------------------
// PTX helpers (compute_100-safe: cp.async / ldmatrix / mma.sync / redux)
// ---------------------------------------------------------------------------
__device__ __forceinline__ uint32_t smem_u32(const void* p) {
    uint32_t a;
    asm("{ .reg .u64 t; cvta.to.shared.u64 t, %1; cvt.u32.u64 %0, t; }"
        : "=r"(a) : "l"(p));
    return a;
}
__device__ __forceinline__ void cp16(uint32_t s, const void* g) {
    asm volatile("cp.async.cg.shared.global [%0], [%1], 16;" :: "r"(s), "l"(g));
}
#define CP_COMMIT() asm volatile("cp.async.commit_group;" ::: "memory")
#define CP_WAIT(n)  asm volatile("cp.async.wait_group %0;" :: "n"(n) : "memory")

__device__ __forceinline__ uint32_t sw128(uint32_t off) {
    return off ^ ((off >> 3) & 0x70);
}
__device__ __forceinline__ void ldsm4(uint32_t* r, uint32_t addr) {
    asm volatile("ldmatrix.sync.aligned.m8n8.x4.shared.b16 {%0,%1,%2,%3}, [%4];"
                 : "=r"(r[0]), "=r"(r[1]), "=r"(r[2]), "=r"(r[3]) : "r"(addr));
}
__device__ __forceinline__ void mma16832s8(int* d, const uint32_t* a, const uint32_t* b) {
    asm volatile(
        "mma.sync.aligned.m16n8k32.row.col.s32.s8.s8.s32 "
        "{%0,%1,%2,%3}, {%4,%5,%6,%7}, {%8,%9}, {%0,%1,%2,%3};"
        : "+r"(d[0]), "+r"(d[1]), "+r"(d[2]), "+r"(d[3])
        : "r"(a[0]), "r"(a[1]), "r"(a[2]), "r"(a[3]), "r"(b[0]), "r"(b[1]));
}

// saturating s8 pack: d = q0 | q1<<8 | q2<<16 | q3<<24
__device__ __forceinline__ uint32_t pack4s8(int q0, int q1, int q2, int q3) {
    uint32_t t, d;
    asm("cvt.pack.sat.s8.s32.b32 %0, %1, %2, %3;" : "=r"(t) : "r"(q3), "r"(q2), "r"(0));
    asm("cvt.pack.sat.s8.s32.b32 %0, %1, %2, %3;" : "=r"(d) : "r"(q1), "r"(q0), "r"(t));
    return d;
}

// Monotone packed argmax key: larger value -> larger pack; equal value ->
// smaller index -> larger pack (first-index tie-break).
__device__ __forceinline__ void atom_pack_max(unsigned long long* p, float v, int idx) {
    const uint32_t b = __float_as_uint(v);
    const uint32_t key = (b & 0x80000000u) ? ~b : (b | 0x80000000u);
    const unsigned long long pk =
        ((unsigned long long)key << 32) | (uint32_t)(0x7FFFFFFFu - idx);
    atomicMax(p, pk);
}

// strip-major flattened tile list helpers
__device__ __forceinline__ void strip_of(int t, int& i, int& d) {
    if (t < 33 * 32) { i = t / 33; d = t - i * 33; }
    else { const int u = t - 33 * 32; i = 32 + u / 32; d = u & 31; }
}
__device__ __forceinline__ int strip_end(int i) {
    return (i < 32) ? (i + 1) * 33 : 33 * 32 + (i - 31) * 32;
}

// ---------------------------------------------------------------------------
// Kernel 0: per-row int8 quantization, warp-per-row.
// Warp max via redux.sync on |x| bit patterns (|x|>=0: IEEE order == u32
// order); s8 packing via cvt.pack.sat (saturation == the +/-127 clamp).
// ---------------------------------------------------------------------------
__global__ __launch_bounds__(256) void quant_kernel(const float* __restrict__ x) {
    const int warp = threadIdx.x >> 5;
    const int lane = threadIdx.x & 31;
    const int row  = blockIdx.x * 8 + warp;

    const float4* rp = reinterpret_cast<const float4*>(x + (size_t)row * DIM) + lane * 4;
    float4 v[4];
#pragma unroll
    for (int q = 0; q < 4; ++q) v[q] = rp[q];

    uint32_t mb = 0;
#pragma unroll
    for (int q = 0; q < 4; ++q) {
        mb = max(mb, __float_as_uint(fabsf(v[q].x)));
        mb = max(mb, __float_as_uint(fabsf(v[q].y)));
        mb = max(mb, __float_as_uint(fabsf(v[q].z)));
        mb = max(mb, __float_as_uint(fabsf(v[q].w)));
    }
    const float m   = __uint_as_float(__reduce_max_sync(0xffffffffu, mb));
    const float inv = 127.0f / m;

    uint4 o4;
    uint32_t* op = &o4.x;
#pragma unroll
    for (int q = 0; q < 4; ++q)
        op[q] = pack4s8(__float2int_rn(v[q].x * inv), __float2int_rn(v[q].y * inv),
                        __float2int_rn(v[q].z * inv), __float2int_rn(v[q].w * inv));
    reinterpret_cast<uint4*>(g_xq)[row * (DIM / 16) + lane] = o4;

    if (lane == 0) {
        g_scale[row] = m * (1.0f / 127.0f);
        g_pack[row]  = 0ull;     // key=0 < any real key
        if (row == 0) g_cnt = 0;
    }
}

// ---------------------------------------------------------------------------
// Kernel 1: symmetric (triangular) int8 mma.sync GEMM + dual-sided argmax.
// PROVEN 90.8us configuration: 148 CTAs x 256 threads, 2x4 warp grid,
// 64x32 warp tile, batched per-chunk fragments. Balanced contiguous ranges
// of the strip-major tile list.
// ---------------------------------------------------------------------------
__global__ __launch_bounds__(256, 1) void gemm_argmax_kernel() {
    extern __shared__ __align__(128) char smem[];
    const uint32_t sb = smem_u32(smem);

    const int tid  = threadIdx.x;
    const int wid  = tid >> 5;
    const int lane = tid & 31;
    const int wr   = wid >> 2;           // warp row (0-1) -> 64 rows
    const int wc   = wid & 3;            // warp col (0-3) -> 32 cols

    const int t_begin = (int)((long long)blockIdx.x * NTILES / NCTA);
    const int t_end   = (int)((long long)(blockIdx.x + 1) * NTILES / NCTA);

    const uint8_t* xq = g_xq;

    const int a_row_lo = ((lane >> 3) & 1) * 8 + (lane & 7);
    const int a_kext   = (lane >> 4) * 16;
    const int b_row_lo = ((lane >> 4) & 1) * 8 + (lane & 7);
    const int b_kext   = ((lane >> 3) & 1) * 16;

    float* sV = reinterpret_cast<float*>(smem + SMO_B);          // scratch [128][4]
    int*   sI = reinterpret_cast<int*>(smem + SMO_B + 2048);

    int t = t_begin;
    while (t < t_end) {
        int strip, d0;
        strip_of(t, strip, d0);
        const int seg_end = min(t_end, strip_end(strip));
        const int NC   = (seg_end - t) * KCH;
        const int m0   = strip * BM;

        // per-segment row scales (candidate-side factor for the column fold)
        float srow[8];
#pragma unroll
        for (int mt = 0; mt < 4; ++mt) {
            const int r0 = m0 + wr * 64 + mt * 16 + (lane >> 2);
            srow[mt * 2]     = g_scale[r0];
            srow[mt * 2 + 1] = g_scale[r0 + 8];
        }

        __syncthreads();   // prior segment fully consumed A & B & scratch

        // ---- A strip: 4 chunks of [128 x 128] int8, SW128 (one group)
#pragma unroll
        for (int kc = 0; kc < KCH; ++kc) {
#pragma unroll
            for (int i = 0; i < 4; ++i) {
                const int u   = i * 256 + tid;       // 16B units
                const int row = u >> 3;
                const int c16 = u & 7;
                cp16(sb + SMO_A + kc * CHB + sw128(row * 128 + c16 * 16),
                     xq + (size_t)(m0 + row) * DIM + kc * KCB + c16 * 16);
            }
        }
        CP_COMMIT();

        // ---- B prologue: chunks 0..2 into slots 0..2
#pragma unroll
        for (int p = 0; p < 3; ++p) {
            const int j  = (strip + d0) & (NSTRIP - 1);  // p<4 -> tile 0
            const int kc = p;
            const int n0 = j * BN;
#pragma unroll
            for (int i = 0; i < 4; ++i) {
                const int u   = i * 256 + tid;
                const int row = u >> 3;
                const int c16 = u & 7;
                cp16(sb + SMO_B + p * CHB + sw128(row * 128 + c16 * 16),
                     xq + (size_t)(n0 + row) * DIM + kc * KCB + c16 * 16);
            }
            CP_COMMIT();
        }
        CP_WAIT(3);          // A landed
        __syncthreads();

        int acc[4][4][4];
#pragma unroll
        for (int mt = 0; mt < 4; ++mt)
#pragma unroll
            for (int nt = 0; nt < 4; ++nt)
#pragma unroll
                for (int k = 0; k < 4; ++k) acc[mt][nt][k] = 0;

        float bestV[8];
        int   bestI[8];
#pragma unroll
        for (int i = 0; i < 8; ++i) { bestV[i] = -3.402823466e38f; bestI[i] = 0; }

        for (int g = 0; g < NC; ++g) {
            CP_WAIT(2);
            __syncthreads();

            const int gn = g + 3;
            if (gn < NC) {
                const int j  = (strip + d0 + (gn >> 2)) & (NSTRIP - 1);
                const int kc = gn & 3;
                const int n0 = j * BN;
                const uint32_t dst = sb + SMO_B + (gn & 3) * CHB;
#pragma unroll
                for (int i = 0; i < 4; ++i) {
                    const int u   = i * 256 + tid;
                    const int row = u >> 3;
                    const int c16 = u & 7;
                    cp16(dst + sw128(row * 128 + c16 * 16),
                         xq + (size_t)(n0 + row) * DIM + kc * KCB + c16 * 16);
                }
            }
            CP_COMMIT();

            // ---- compute chunk g: batch ALL fragments, then 64 mma
            const uint32_t abase = sb + SMO_A + (g & 3) * CHB;
            const uint32_t bbase = sb + SMO_B + (g & 3) * CHB;
            uint32_t afr[4][4][4];    // [ks][mt][4]
            uint32_t bfr[4][2][4];    // [ks][h][4]
#pragma unroll
            for (int ks = 0; ks < 4; ++ks) {
#pragma unroll
                for (int mt = 0; mt < 4; ++mt) {
                    const int row = wr * 64 + mt * 16 + a_row_lo;
                    ldsm4(afr[ks][mt], abase + sw128(row * 128 + ks * 32 + a_kext));
                }
#pragma unroll
                for (int h2 = 0; h2 < 2; ++h2) {
                    const int row = wc * 32 + h2 * 16 + b_row_lo;
                    ldsm4(bfr[ks][h2], bbase + sw128(row * 128 + ks * 32 + b_kext));
                }
            }
#pragma unroll
            for (int ks = 0; ks < 4; ++ks)
#pragma unroll
                for (int mt = 0; mt < 4; ++mt)
#pragma unroll
                    for (int nt = 0; nt < 4; ++nt)
                        mma16832s8(acc[mt][nt], afr[ks][mt],
                                   &bfr[ks][nt >> 1][(nt & 1) * 2]);

            // ---- tile finished (K=512): dual-sided fold, reset acc
            if ((g & 3) == 3) {
                const int d    = d0 + (g >> 2);
                const int j    = (strip + d) & (NSTRIP - 1);
                const int nc0  = j * BN + wc * 32;
                const bool diag = (d == 0);

                float scs[8];
#pragma unroll
                for (int nt = 0; nt < 4; ++nt) {
                    const int c0 = nc0 + nt * 8 + (lane & 3) * 2;
                    scs[nt * 2]     = g_scale[c0];
                    scs[nt * 2 + 1] = g_scale[c0 + 1];
                }

                // row side: v = s_col * dot (missing s_row constant per slot)
#pragma unroll
                for (int mt = 0; mt < 4; ++mt) {
                    const int row0 = m0 + wr * 64 + mt * 16 + (lane >> 2);
                    const int row1 = row0 + 8;
#pragma unroll
                    for (int nt = 0; nt < 4; ++nt) {
                        const int c0 = nc0 + nt * 8 + (lane & 3) * 2;
                        const float v00 = (float)acc[mt][nt][0] * scs[nt * 2];
                        const float v01 = (float)acc[mt][nt][1] * scs[nt * 2 + 1];
                        const float v10 = (float)acc[mt][nt][2] * scs[nt * 2];
                        const float v11 = (float)acc[mt][nt][3] * scs[nt * 2 + 1];
                        const int b0 = mt * 2, b1 = mt * 2 + 1;
                        if (c0 != row0 && v00 > bestV[b0]) { bestV[b0] = v00; bestI[b0] = c0; }
                        if (c0 + 1 != row0 && v01 > bestV[b0]) { bestV[b0] = v01; bestI[b0] = c0 + 1; }
                        if (c0 != row1 && v10 > bestV[b1]) { bestV[b1] = v10; bestI[b1] = c0; }
                        if (c0 + 1 != row1 && v11 > bestV[b1]) { bestV[b1] = v11; bestI[b1] = c0 + 1; }
                    }
                }

                // column side: v = s_row * dot, skipped for diagonal tile
                if (!diag) {
                    float cV[8];
                    int   cI[8];
#pragma unroll
                    for (int k = 0; k < 8; ++k) { cV[k] = -3.402823466e38f; cI[k] = 0; }
#pragma unroll
                    for (int mt = 0; mt < 4; ++mt) {
                        const int row0 = m0 + wr * 64 + mt * 16 + (lane >> 2);
                        const int row1 = row0 + 8;
                        const float s0 = srow[mt * 2], s1 = srow[mt * 2 + 1];
#pragma unroll
                        for (int nt = 0; nt < 4; ++nt) {
                            const int k0 = nt * 2, k1 = nt * 2 + 1;
                            const float v00 = (float)acc[mt][nt][0] * s0;
                            const float v01 = (float)acc[mt][nt][1] * s0;
                            const float v10 = (float)acc[mt][nt][2] * s1;
                            const float v11 = (float)acc[mt][nt][3] * s1;
                            if (v00 > cV[k0]) { cV[k0] = v00; cI[k0] = row0; }
                            if (v10 > cV[k0]) { cV[k0] = v10; cI[k0] = row1; }
                            if (v01 > cV[k1]) { cV[k1] = v01; cI[k1] = row0; }
                            if (v11 > cV[k1]) { cV[k1] = v11; cI[k1] = row1; }
                        }
                    }
#pragma unroll
                    for (int k = 0; k < 8; ++k) {
                        float v = cV[k];
                        int   ci = cI[k];
#pragma unroll
                        for (int o = 4; o <= 16; o <<= 1) {
                            const float ov = __shfl_xor_sync(0xffffffffu, v, o);
                            const int   oi = __shfl_xor_sync(0xffffffffu, ci, o);
                            if (ov > v || (ov == v && oi < ci)) { v = ov; ci = oi; }
                        }
                        if ((lane >> 2) == 0) {
                            const int col = nc0 + (k >> 1) * 8 + (lane & 3) * 2 + (k & 1);
                            atom_pack_max(&g_pack[col], v, ci);
                        }
                    }
                }

#pragma unroll
                for (int mt = 0; mt < 4; ++mt)
#pragma unroll
                    for (int nt = 0; nt < 4; ++nt) {
                        acc[mt][nt][0] = 0; acc[mt][nt][1] = 0;
                        acc[mt][nt][2] = 0; acc[mt][nt][3] = 0;
                    }
            }
        }

        // ---- flush row-side bests for this strip segment
        __syncthreads();   // ring quiescent -> reuse as scratch
#pragma unroll
        for (int b = 0; b < 8; ++b) {
            float v = bestV[b];
            int   i = bestI[b];
#pragma unroll
            for (int o = 2; o > 0; o >>= 1) {
                const float ov = __shfl_xor_sync(0xffffffffu, v, o);
                const int   oi = __shfl_xor_sync(0xffffffffu, i, o);
                if (ov > v || (ov == v && oi < i)) { v = ov; i = oi; }
            }
            if ((lane & 3) == 0) {
                const int lrow = wr * 64 + (b >> 1) * 16 + (b & 1) * 8 + (lane >> 2);
                sV[lrow * 4 + wc] = v;
                sI[lrow * 4 + wc] = i;
            }
        }
        __syncthreads();
        if (tid < BM) {
            float v = sV[tid * 4];
            int   i = sI[tid * 4];
#pragma unroll
            for (int q = 1; q < 4; ++q) {
                const float ov = sV[tid * 4 + q];
                const int   oi = sI[tid * 4 + q];
                if (ov > v || (ov == v && oi < i)) { v = ov; i = oi; }
            }
            atom_pack_max(&g_pack[m0 + tid], v, i);
        }

        t = seg_end;
    }
}

// ---------------------------------------------------------------------------
// Kernel 2: rho (exact fp32), warp-per-row + block-level fused loss.
// ---------------------------------------------------------------------------
__global__ __launch_bounds__(256) void rho_loss_kernel(const float* __restrict__ x,
                                                       float* __restrict__ out) {
    const int warp = threadIdx.x >> 5;
    const int lane = threadIdx.x & 31;
    const int row  = blockIdx.x * 8 + warp;

    const unsigned long long p = g_pack[row];
    const int nn = 0x7FFFFFFF - (int)(uint32_t)(p & 0xFFFFFFFFull);

    const float4* ra = reinterpret_cast<const float4*>(x + (size_t)row * DIM);
    const float4* rb = reinterpret_cast<const float4*>(x + (size_t)nn  * DIM);
    float s = 0.0f;
#pragma unroll
    for (int q = 0; q < 4; ++q) {
        const float4 a = ra[lane + 32 * q];
        const float4 b = rb[lane + 32 * q];
        const float dx = a.x - b.x + 1e-6f;
        const float dy = a.y - b.y + 1e-6f;
        const float dz = a.z - b.z + 1e-6f;
        const float dw = a.w - b.w + 1e-6f;
        s += dx * dx + dy * dy + dz * dz + dw * dw;
    }
#pragma unroll
    for (int o = 16; o > 0; o >>= 1) s += __shfl_xor_sync(0xffffffffu, s, o);

    if (lane == 0) g_term[row] = logf(sqrtf(s) + 1e-8f);

    __shared__ int slast;
    __shared__ float ws[8];
    __threadfence();
    __syncthreads();
    if (threadIdx.x == 0) {
        const int old = atomicAdd(&g_cnt, 8);
        slast = (old == NROW - 8);
    }
    __syncthreads();

    if (slast) {   // last block: deterministic fixed-order global reduction
        __threadfence();
        float acc = 0.0f;
        for (int i = threadIdx.x; i < NROW; i += 256) acc += g_term[i];
#pragma unroll
        for (int o = 16; o > 0; o >>= 1) acc += __shfl_xor_sync(0xffffffffu, acc, o);
        if (lane == 0) ws[warp] = acc;
        __syncthreads();
        if (threadIdx.x == 0) {
            float tot = 0.0f;
#pragma unroll
            for (int w = 0; w < 8; ++w) tot += ws[w];
            out[0] = -tot / (float)NROW;
        }
    }
}

extern "C" void kernel_launch(void* const* d_in, const int* in_sizes, int n_in,
                              void* d_out, int out_size) {
    (void)in_sizes; (void)n_in; (void)out_size;
    const float* x = (const float*)d_in[0];
    float* out = (float*)d_out;

    cudaFuncSetAttribute(gemm_argmax_kernel,
                         cudaFuncAttributeMaxDynamicSharedMemorySize, SMEM_SZ);

    quant_kernel<<<NROW / 8, 256>>>(x);
    gemm_argmax_kernel<<<NCTA, 256, SMEM_SZ>>>();
    rho_loss_kernel<<<NROW / 8, 256>>>(x, out);
}

// round 13
// speedup vs baseline: 1.1428x; 1.0483x over previous
#include <cuda_runtime.h>
#include <math.h>
#include <stdint.h>

// ---------------------------------------------------------------------------
// Problem constants (x: [8192, 512] fp32)
// ---------------------------------------------------------------------------
constexpr int NROW = 8192;
constexpr int DIM  = 512;

constexpr int BM   = 128;           // rows per strip
constexpr int BN   = 128;           // cols per tile
constexpr int KCB  = 128;           // K per smem chunk (128 int8 = 128B rows)
constexpr int KCH  = DIM / KCB;     // 4 K-chunks per tile
constexpr int NSTRIP = NROW / BM;   // 64 strips
constexpr int CHB  = BM * KCB;      // 16384 B per chunk tile
constexpr int NTILES = 33 * 32 + 32 * 32;   // 2080
constexpr int NCTA   = 148;

constexpr int SMO_A = 0;                       // 4 * 16KB resident A strip
constexpr int SMO_B = SMO_A + KCH * CHB;       // 4-slot B ring
constexpr int SMEM_SZ = SMO_B + 4 * CHB;       // 131072 B

// Scratch (no allocations allowed anywhere)
__device__ uint8_t g_xq[NROW * DIM];           // int8 quantized x
__device__ float   g_scale[NROW];              // per-row dequant scale
__device__ unsigned long long g_pack[NROW];    // packed (valkey<<32)|(0x7FFFFFFF-idx)
__device__ float g_term[NROW];
__device__ int   g_cnt;

// ---------------------------------------------------------------------------
// PTX helpers (compute_100-safe: cp.async / ldmatrix / mma.sync / redux)
// ---------------------------------------------------------------------------
__device__ __forceinline__ uint32_t smem_u32(const void* p) {
    uint32_t a;
    asm("{ .reg .u64 t; cvta.to.shared.u64 t, %1; cvt.u32.u64 %0, t; }"
        : "=r"(a) : "l"(p));
    return a;
}
__device__ __forceinline__ void cp16(uint32_t s, const void* g) {
    asm volatile("cp.async.cg.shared.global [%0], [%1], 16;" :: "r"(s), "l"(g));
}
#define CP_COMMIT() asm volatile("cp.async.commit_group;" ::: "memory")
#define CP_WAIT(n)  asm volatile("cp.async.wait_group %0;" :: "n"(n) : "memory")

__device__ __forceinline__ uint32_t sw128(uint32_t off) {
    return off ^ ((off >> 3) & 0x70);
}
__device__ __forceinline__ void ldsm4(uint32_t* r, uint32_t addr) {
    asm volatile("ldmatrix.sync.aligned.m8n8.x4.shared.b16 {%0,%1,%2,%3}, [%4];"
                 : "=r"(r[0]), "=r"(r[1]), "=r"(r[2]), "=r"(r[3]) : "r"(addr));
}
__device__ __forceinline__ void mma16832s8(int* d, const uint32_t* a, const uint32_t* b) {
    asm volatile(
        "mma.sync.aligned.m16n8k32.row.col.s32.s8.s8.s32 "
        "{%0,%1,%2,%3}, {%4,%5,%6,%7}, {%8,%9}, {%0,%1,%2,%3};"
        : "+r"(d[0]), "+r"(d[1]), "+r"(d[2]), "+r"(d[3])
        : "r"(a[0]), "r"(a[1]), "r"(a[2]), "r"(a[3]), "r"(b[0]), "r"(b[1]));
}

// saturating s8 pack: d = q0 | q1<<8 | q2<<16 | q3<<24
__device__ __forceinline__ uint32_t pack4s8(int q0, int q1, int q2, int q3) {
    uint32_t t, d;
    asm("cvt.pack.sat.s8.s32.b32 %0, %1, %2, %3;" : "=r"(t) : "r"(q3), "r"(q2), "r"(0));
    asm("cvt.pack.sat.s8.s32.b32 %0, %1, %2, %3;" : "=r"(d) : "r"(q1), "r"(q0), "r"(t));
    return d;
}

// Monotone u32 key for float ordering: larger float -> larger key.
__device__ __forceinline__ uint32_t fkey(float v) {
    const uint32_t b = __float_as_uint(v);
    return (b & 0x80000000u) ? ~b : (b | 0x80000000u);
}

// Monotone packed argmax key: larger value -> larger pack; equal value ->
// smaller index -> larger pack (first-index tie-break).
__device__ __forceinline__ void atom_pack_max(unsigned long long* p, float v, int idx) {
    const unsigned long long pk =
        ((unsigned long long)fkey(v) << 32) | (uint32_t)(0x7FFFFFFFu - idx);
    atomicMax(p, pk);
}

// strip-major flattened tile list helpers
__device__ __forceinline__ void strip_of(int t, int& i, int& d) {
    if (t < 33 * 32) { i = t / 33; d = t - i * 33; }
    else { const int u = t - 33 * 32; i = 32 + u / 32; d = u & 31; }
}
__device__ __forceinline__ int strip_end(int i) {
    return (i < 32) ? (i + 1) * 33 : 33 * 32 + (i - 31) * 32;
}

// ---------------------------------------------------------------------------
// Kernel 0: per-row int8 quantization, warp-per-row.
// ---------------------------------------------------------------------------
__global__ __launch_bounds__(256) void quant_kernel(const float* __restrict__ x) {
    const int warp = threadIdx.x >> 5;
    const int lane = threadIdx.x & 31;
    const int row  = blockIdx.x * 8 + warp;

    const float4* rp = reinterpret_cast<const float4*>(x + (size_t)row * DIM) + lane * 4;
    float4 v[4];
#pragma unroll
    for (int q = 0; q < 4; ++q) v[q] = rp[q];

    uint32_t mb = 0;
#pragma unroll
    for (int q = 0; q < 4; ++q) {
        mb = max(mb, __float_as_uint(fabsf(v[q].x)));
        mb = max(mb, __float_as_uint(fabsf(v[q].y)));
        mb = max(mb, __float_as_uint(fabsf(v[q].z)));
        mb = max(mb, __float_as_uint(fabsf(v[q].w)));
    }
    const float m   = __uint_as_float(__reduce_max_sync(0xffffffffu, mb));
    const float inv = 127.0f / m;

    uint4 o4;
    uint32_t* op = &o4.x;
#pragma unroll
    for (int q = 0; q < 4; ++q)
        op[q] = pack4s8(__float2int_rn(v[q].x * inv), __float2int_rn(v[q].y * inv),
                        __float2int_rn(v[q].z * inv), __float2int_rn(v[q].w * inv));
    reinterpret_cast<uint4*>(g_xq)[row * (DIM / 16) + lane] = o4;

    if (lane == 0) {
        g_scale[row] = m * (1.0f / 127.0f);
        g_pack[row]  = 0ull;     // key=0 < any real key
        if (row == 0) g_cnt = 0;
    }
}

// ---------------------------------------------------------------------------
// Kernel 1: symmetric (triangular) int8 mma.sync GEMM + dual-sided argmax.
// 148 CTAs x 256 threads, 2x4 warp grid, 64x32 warp tile, batched fragments.
// Column-side fold uses a packed 32-bit (truncated-key | 127-localrow)
// shfl+umax reduction (3 instr/level vs 5) — key truncation (low 7 mantissa
// bits) perturbs comparisons by <=2^-16 relative, far below int8 noise.
// ---------------------------------------------------------------------------
__global__ __launch_bounds__(256, 1) void gemm_argmax_kernel() {
    extern __shared__ __align__(128) char smem[];
    const uint32_t sb = smem_u32(smem);

    const int tid  = threadIdx.x;
    const int wid  = tid >> 5;
    const int lane = tid & 31;
    const int wr   = wid >> 2;           // warp row (0-1) -> 64 rows
    const int wc   = wid & 3;            // warp col (0-3) -> 32 cols

    const int t_begin = (int)((long long)blockIdx.x * NTILES / NCTA);
    const int t_end   = (int)((long long)(blockIdx.x + 1) * NTILES / NCTA);

    const uint8_t* xq = g_xq;

    const int a_row_lo = ((lane >> 3) & 1) * 8 + (lane & 7);
    const int a_kext   = (lane >> 4) * 16;
    const int b_row_lo = ((lane >> 4) & 1) * 8 + (lane & 7);
    const int b_kext   = ((lane >> 3) & 1) * 16;

    float* sV = reinterpret_cast<float*>(smem + SMO_B);          // scratch [128][4]
    int*   sI = reinterpret_cast<int*>(smem + SMO_B + 2048);

    int t = t_begin;
    while (t < t_end) {
        int strip, d0;
        strip_of(t, strip, d0);
        const int seg_end = min(t_end, strip_end(strip));
        const int NC   = (seg_end - t) * KCH;
        const int m0   = strip * BM;

        // per-segment row scales (candidate-side factor for the column fold)
        float srow[8];
#pragma unroll
        for (int mt = 0; mt < 4; ++mt) {
            const int r0 = m0 + wr * 64 + mt * 16 + (lane >> 2);
            srow[mt * 2]     = g_scale[r0];
            srow[mt * 2 + 1] = g_scale[r0 + 8];
        }

        __syncthreads();   // prior segment fully consumed A & B & scratch

        // ---- A strip: 4 chunks of [128 x 128] int8, SW128 (one group)
#pragma unroll
        for (int kc = 0; kc < KCH; ++kc) {
#pragma unroll
            for (int i = 0; i < 4; ++i) {
                const int u   = i * 256 + tid;       // 16B units
                const int row = u >> 3;
                const int c16 = u & 7;
                cp16(sb + SMO_A + kc * CHB + sw128(row * 128 + c16 * 16),
                     xq + (size_t)(m0 + row) * DIM + kc * KCB + c16 * 16);
            }
        }
        CP_COMMIT();

        // ---- B prologue: chunks 0..2 into slots 0..2
#pragma unroll
        for (int p = 0; p < 3; ++p) {
            const int j  = (strip + d0) & (NSTRIP - 1);  // p<4 -> tile 0
            const int kc = p;
            const int n0 = j * BN;
#pragma unroll
            for (int i = 0; i < 4; ++i) {
                const int u   = i * 256 + tid;
                const int row = u >> 3;
                const int c16 = u & 7;
                cp16(sb + SMO_B + p * CHB + sw128(row * 128 + c16 * 16),
                     xq + (size_t)(n0 + row) * DIM + kc * KCB + c16 * 16);
            }
            CP_COMMIT();
        }
        CP_WAIT(3);          // A landed
        __syncthreads();

        int acc[4][4][4];
#pragma unroll
        for (int mt = 0; mt < 4; ++mt)
#pragma unroll
            for (int nt = 0; nt < 4; ++nt)
#pragma unroll
                for (int k = 0; k < 4; ++k) acc[mt][nt][k] = 0;

        float bestV[8];
        int   bestI[8];
#pragma unroll
        for (int i = 0; i < 8; ++i) { bestV[i] = -3.402823466e38f; bestI[i] = 0; }

        for (int g = 0; g < NC; ++g) {
            CP_WAIT(2);
            __syncthreads();

            const int gn = g + 3;
            if (gn < NC) {
                const int j  = (strip + d0 + (gn >> 2)) & (NSTRIP - 1);
                const int kc = gn & 3;
                const int n0 = j * BN;
                const uint32_t dst = sb + SMO_B + (gn & 3) * CHB;
#pragma unroll
                for (int i = 0; i < 4; ++i) {
                    const int u   = i * 256 + tid;
                    const int row = u >> 3;
                    const int c16 = u & 7;
                    cp16(dst + sw128(row * 128 + c16 * 16),
                         xq + (size_t)(n0 + row) * DIM + kc * KCB + c16 * 16);
                }
            }
            CP_COMMIT();

            // ---- compute chunk g: batch ALL fragments, then 64 mma
            const uint32_t abase = sb + SMO_A + (g & 3) * CHB;
            const uint32_t bbase = sb + SMO_B + (g & 3) * CHB;
            uint32_t afr[4][4][4];    // [ks][mt][4]
            uint32_t bfr[4][2][4];    // [ks][h][4]
#pragma unroll
            for (int ks = 0; ks < 4; ++ks) {
#pragma unroll
                for (int mt = 0; mt < 4; ++mt) {
                    const int row = wr * 64 + mt * 16 + a_row_lo;
                    ldsm4(afr[ks][mt], abase + sw128(row * 128 + ks * 32 + a_kext));
                }
#pragma unroll
                for (int h2 = 0; h2 < 2; ++h2) {
                    const int row = wc * 32 + h2 * 16 + b_row_lo;
                    ldsm4(bfr[ks][h2], bbase + sw128(row * 128 + ks * 32 + b_kext));
                }
            }
#pragma unroll
            for (int ks = 0; ks < 4; ++ks)
#pragma unroll
                for (int mt = 0; mt < 4; ++mt)
#pragma unroll
                    for (int nt = 0; nt < 4; ++nt)
                        mma16832s8(acc[mt][nt], afr[ks][mt],
                                   &bfr[ks][nt >> 1][(nt & 1) * 2]);

            // ---- tile finished (K=512): dual-sided fold, reset acc
            if ((g & 3) == 3) {
                const int d    = d0 + (g >> 2);
                const int j    = (strip + d) & (NSTRIP - 1);
                const int nc0  = j * BN + wc * 32;
                const bool diag = (d == 0);

                float scs[8];
#pragma unroll
                for (int nt = 0; nt < 4; ++nt) {
                    const int c0 = nc0 + nt * 8 + (lane & 3) * 2;
                    scs[nt * 2]     = g_scale[c0];
                    scs[nt * 2 + 1] = g_scale[c0 + 1];
                }

                // row side: v = s_col * dot (missing s_row constant per slot)
#pragma unroll
                for (int mt = 0; mt < 4; ++mt) {
                    const int row0 = m0 + wr * 64 + mt * 16 + (lane >> 2);
                    const int row1 = row0 + 8;
#pragma unroll
                    for (int nt = 0; nt < 4; ++nt) {
                        const int c0 = nc0 + nt * 8 + (lane & 3) * 2;
                        const float v00 = (float)acc[mt][nt][0] * scs[nt * 2];
                        const float v01 = (float)acc[mt][nt][1] * scs[nt * 2 + 1];
                        const float v10 = (float)acc[mt][nt][2] * scs[nt * 2];
                        const float v11 = (float)acc[mt][nt][3] * scs[nt * 2 + 1];
                        const int b0 = mt * 2, b1 = mt * 2 + 1;
                        if (c0 != row0 && v00 > bestV[b0]) { bestV[b0] = v00; bestI[b0] = c0; }
                        if (c0 + 1 != row0 && v01 > bestV[b0]) { bestV[b0] = v01; bestI[b0] = c0 + 1; }
                        if (c0 != row1 && v10 > bestV[b1]) { bestV[b1] = v10; bestI[b1] = c0; }
                        if (c0 + 1 != row1 && v11 > bestV[b1]) { bestV[b1] = v11; bestI[b1] = c0 + 1; }
                    }
                }

                // column side: v = s_row * dot, skipped for diagonal tile.
                // Local best per thread (value + local row), then packed
                // 32-bit shfl+umax reduction over the 8 lanes per column.
                if (!diag) {
                    float cV[8];
                    int   cL[8];   // local row within strip (0..127)
#pragma unroll
                    for (int k = 0; k < 8; ++k) { cV[k] = -3.402823466e38f; cL[k] = 0; }
#pragma unroll
                    for (int mt = 0; mt < 4; ++mt) {
                        const int l0 = wr * 64 + mt * 16 + (lane >> 2);
                        const int l1 = l0 + 8;
                        const float s0 = srow[mt * 2], s1 = srow[mt * 2 + 1];
#pragma unroll
                        for (int nt = 0; nt < 4; ++nt) {
                            const int k0 = nt * 2, k1 = nt * 2 + 1;
                            const float v00 = (float)acc[mt][nt][0] * s0;
                            const float v01 = (float)acc[mt][nt][1] * s0;
                            const float v10 = (float)acc[mt][nt][2] * s1;
                            const float v11 = (float)acc[mt][nt][3] * s1;
                            if (v00 > cV[k0]) { cV[k0] = v00; cL[k0] = l0; }
                            if (v10 > cV[k0]) { cV[k0] = v10; cL[k0] = l1; }
                            if (v01 > cV[k1]) { cV[k1] = v01; cL[k1] = l0; }
                            if (v11 > cV[k1]) { cV[k1] = v11; cL[k1] = l1; }
                        }
                    }
#pragma unroll
                    for (int k = 0; k < 8; ++k) {
                        // packed: truncated monotone key (top 25b) | 127-lrow
                        uint32_t pk = (fkey(cV[k]) & 0xFFFFFF80u)
                                      | (uint32_t)(127 - cL[k]);
#pragma unroll
                        for (int o = 4; o <= 16; o <<= 1)
                            pk = max(pk, __shfl_xor_sync(0xffffffffu, pk, o));
                        if ((lane >> 2) == 0) {
                            const int lrow = 127 - (int)(pk & 0x7F);
                            const int col  = nc0 + (k >> 1) * 8 + (lane & 3) * 2 + (k & 1);
                            const unsigned long long pk64 =
                                ((unsigned long long)(pk & 0xFFFFFF80u) << 32) |
                                (uint32_t)(0x7FFFFFFFu - (m0 + lrow));
                            atomicMax(&g_pack[col], pk64);
                        }
                    }
                }

#pragma unroll
                for (int mt = 0; mt < 4; ++mt)
#pragma unroll
                    for (int nt = 0; nt < 4; ++nt) {
                        acc[mt][nt][0] = 0; acc[mt][nt][1] = 0;
                        acc[mt][nt][2] = 0; acc[mt][nt][3] = 0;
                    }
            }
        }

        // ---- flush row-side bests for this strip segment
        __syncthreads();   // ring quiescent -> reuse as scratch
#pragma unroll
        for (int b = 0; b < 8; ++b) {
            float v = bestV[b];
            int   i = bestI[b];
#pragma unroll
            for (int o = 2; o > 0; o >>= 1) {
                const float ov = __shfl_xor_sync(0xffffffffu, v, o);
                const int   oi = __shfl_xor_sync(0xffffffffu, i, o);
                if (ov > v || (ov == v && oi < i)) { v = ov; i = oi; }
            }
            if ((lane & 3) == 0) {
                const int lrow = wr * 64 + (b >> 1) * 16 + (b & 1) * 8 + (lane >> 2);
                sV[lrow * 4 + wc] = v;
                sI[lrow * 4 + wc] = i;
            }
        }
        __syncthreads();
        if (tid < BM) {
            float v = sV[tid * 4];
            int   i = sI[tid * 4];
#pragma unroll
            for (int q = 1; q < 4; ++q) {
                const float ov = sV[tid * 4 + q];
                const int   oi = sI[tid * 4 + q];
                if (ov > v || (ov == v && oi < i)) { v = ov; i = oi; }
            }
            atom_pack_max(&g_pack[m0 + tid], v, i);
        }

        t = seg_end;
    }
}

// ---------------------------------------------------------------------------
// Kernel 2: rho (exact fp32), warp-per-row + block-level fused loss.
// ---------------------------------------------------------------------------
__global__ __launch_bounds__(256) void rho_loss_kernel(const float* __restrict__ x,
                                                       float* __restrict__ out) {
    const int warp = threadIdx.x >> 5;
    const int lane = threadIdx.x & 31;
    const int row  = blockIdx.x * 8 + warp;

    const unsigned long long p = g_pack[row];
    const int nn = 0x7FFFFFFF - (int)(uint32_t)(p & 0xFFFFFFFFull);

    const float4* ra = reinterpret_cast<const float4*>(x + (size_t)row * DIM);
    const float4* rb = reinterpret_cast<const float4*>(x + (size_t)nn  * DIM);
    float s = 0.0f;
#pragma unroll
    for (int q = 0; q < 4; ++q) {
        const float4 a = ra[lane + 32 * q];
        const float4 b = rb[lane + 32 * q];
        const float dx = a.x - b.x + 1e-6f;
        const float dy = a.y - b.y + 1e-6f;
        const float dz = a.z - b.z + 1e-6f;
        const float dw = a.w - b.w + 1e-6f;
        s += dx * dx + dy * dy + dz * dz + dw * dw;
    }
#pragma unroll
    for (int o = 16; o > 0; o >>= 1) s += __shfl_xor_sync(0xffffffffu, s, o);

    if (lane == 0) g_term[row] = logf(sqrtf(s) + 1e-8f);

    __shared__ int slast;
    __shared__ float ws[8];
    __threadfence();
    __syncthreads();
    if (threadIdx.x == 0) {
        const int old = atomicAdd(&g_cnt, 8);
        slast = (old == NROW - 8);
    }
    __syncthreads();

    if (slast) {   // last block: deterministic fixed-order global reduction
        __threadfence();
        float acc = 0.0f;
        for (int i = threadIdx.x; i < NROW; i += 256) acc += g_term[i];
#pragma unroll
        for (int o = 16; o > 0; o >>= 1) acc += __shfl_xor_sync(0xffffffffu, acc, o);
        if (lane == 0) ws[warp] = acc;
        __syncthreads();
        if (threadIdx.x == 0) {
            float tot = 0.0f;
#pragma unroll
            for (int w = 0; w < 8; ++w) tot += ws[w];
            out[0] = -tot / (float)NROW;
        }
    }
}

extern "C" void kernel_launch(void* const* d_in, const int* in_sizes, int n_in,
                              void* d_out, int out_size) {
    (void)in_sizes; (void)n_in; (void)out_size;
    const float* x = (const float*)d_in[0];
    float* out = (float*)d_out;

    cudaFuncSetAttribute(gemm_argmax_kernel,
                         cudaFuncAttributeMaxDynamicSharedMemorySize, SMEM_SZ);

    quant_kernel<<<NROW / 8, 256>>>(x);
    gemm_argmax_kernel<<<NCTA, 256, SMEM_SZ>>>();
    rho_loss_kernel<<<NROW / 8, 256>>>(x, out);
}

// round 14
// speedup vs baseline: 1.1667x; 1.0209x over previous
#include <cuda_runtime.h>
#include <math.h>
#include <stdint.h>

// ---------------------------------------------------------------------------
// Problem constants (x: [8192, 512] fp32)
// ---------------------------------------------------------------------------
constexpr int NROW = 8192;
constexpr int DIM  = 512;

constexpr int BM   = 128;           // rows per strip
constexpr int BN   = 128;           // cols per tile
constexpr int KCB  = 128;           // K per smem chunk (128 int8 = 128B rows)
constexpr int KCH  = DIM / KCB;     // 4 K-chunks per tile
constexpr int NSTRIP = NROW / BM;   // 64 strips
constexpr int CHB  = BM * KCB;      // 16384 B per chunk tile
constexpr int NTILES = 33 * 32 + 32 * 32;   // 2080
constexpr int NCTA   = 148;

constexpr int SMO_A = 0;                       // 4 * 16KB resident A strip
constexpr int SMO_B = SMO_A + KCH * CHB;       // 4-slot B ring
constexpr int SMEM_SZ = SMO_B + 4 * CHB;       // 131072 B

// Scratch (no allocations allowed anywhere)
__device__ uint8_t g_xq[NROW * DIM];           // int8 quantized x
__device__ float   g_scale[NROW];              // per-row dequant scale
__device__ unsigned long long g_pack[NROW];    // packed (valkey<<32)|(0x7FFFFFFF-idx)
__device__ float g_term[NROW];
__device__ int   g_cnt;

// ---------------------------------------------------------------------------
// PTX helpers (compute_100-safe: cp.async / ldmatrix / mma.sync / redux)
// ---------------------------------------------------------------------------
__device__ __forceinline__ uint32_t smem_u32(const void* p) {
    uint32_t a;
    asm("{ .reg .u64 t; cvta.to.shared.u64 t, %1; cvt.u32.u64 %0, t; }"
        : "=r"(a) : "l"(p));
    return a;
}
__device__ __forceinline__ void cp16(uint32_t s, const void* g) {
    asm volatile("cp.async.cg.shared.global [%0], [%1], 16;" :: "r"(s), "l"(g));
}
#define CP_COMMIT() asm volatile("cp.async.commit_group;" ::: "memory")
#define CP_WAIT(n)  asm volatile("cp.async.wait_group %0;" :: "n"(n) : "memory")

__device__ __forceinline__ uint32_t sw128(uint32_t off) {
    return off ^ ((off >> 3) & 0x70);
}
__device__ __forceinline__ void ldsm4(uint32_t* r, uint32_t addr) {
    asm volatile("ldmatrix.sync.aligned.m8n8.x4.shared.b16 {%0,%1,%2,%3}, [%4];"
                 : "=r"(r[0]), "=r"(r[1]), "=r"(r[2]), "=r"(r[3]) : "r"(addr));
}
__device__ __forceinline__ void mma16832s8(int* d, const uint32_t* a, const uint32_t* b) {
    asm volatile(
        "mma.sync.aligned.m16n8k32.row.col.s32.s8.s8.s32 "
        "{%0,%1,%2,%3}, {%4,%5,%6,%7}, {%8,%9}, {%0,%1,%2,%3};"
        : "+r"(d[0]), "+r"(d[1]), "+r"(d[2]), "+r"(d[3])
        : "r"(a[0]), "r"(a[1]), "r"(a[2]), "r"(a[3]), "r"(b[0]), "r"(b[1]));
}

// saturating s8 pack: d = q0 | q1<<8 | q2<<16 | q3<<24
__device__ __forceinline__ uint32_t pack4s8(int q0, int q1, int q2, int q3) {
    uint32_t t, d;
    asm("cvt.pack.sat.s8.s32.b32 %0, %1, %2, %3;" : "=r"(t) : "r"(q3), "r"(q2), "r"(0));
    asm("cvt.pack.sat.s8.s32.b32 %0, %1, %2, %3;" : "=r"(d) : "r"(q1), "r"(q0), "r"(t));
    return d;
}

// Monotone u32 key for float ordering: larger float -> larger key.
__device__ __forceinline__ uint32_t fkey(float v) {
    const uint32_t b = __float_as_uint(v);
    return (b & 0x80000000u) ? ~b : (b | 0x80000000u);
}

// Monotone packed argmax key: larger value -> larger pack; equal value ->
// smaller index -> larger pack (first-index tie-break).
__device__ __forceinline__ void atom_pack_max(unsigned long long* p, float v, int idx) {
    const unsigned long long pk =
        ((unsigned long long)fkey(v) << 32) | (uint32_t)(0x7FFFFFFFu - idx);
    atomicMax(p, pk);
}

// strip-major flattened tile list helpers
__device__ __forceinline__ void strip_of(int t, int& i, int& d) {
    if (t < 33 * 32) { i = t / 33; d = t - i * 33; }
    else { const int u = t - 33 * 32; i = 32 + u / 32; d = u & 31; }
}
__device__ __forceinline__ int strip_end(int i) {
    return (i < 32) ? (i + 1) * 33 : 33 * 32 + (i - 31) * 32;
}

// ---------------------------------------------------------------------------
// Kernel 0: per-row int8 quantization, warp-per-row, FULLY COALESCED:
// lane reads float4 at [lane + 32*q] (128B per load instruction) and stores
// the matching packed u32 at [lane + 32*q] (128B per store instruction).
// ---------------------------------------------------------------------------
__global__ __launch_bounds__(256) void quant_kernel(const float* __restrict__ x) {
    const int warp = threadIdx.x >> 5;
    const int lane = threadIdx.x & 31;
    const int row  = blockIdx.x * 8 + warp;

    const float4* rp = reinterpret_cast<const float4*>(x + (size_t)row * DIM);
    float4 v[4];
#pragma unroll
    for (int q = 0; q < 4; ++q) v[q] = rp[lane + 32 * q];

    uint32_t mb = 0;
#pragma unroll
    for (int q = 0; q < 4; ++q) {
        mb = max(mb, __float_as_uint(fabsf(v[q].x)));
        mb = max(mb, __float_as_uint(fabsf(v[q].y)));
        mb = max(mb, __float_as_uint(fabsf(v[q].z)));
        mb = max(mb, __float_as_uint(fabsf(v[q].w)));
    }
    const float m   = __uint_as_float(__reduce_max_sync(0xffffffffu, mb));
    const float inv = 127.0f / m;

    uint32_t* out32 = reinterpret_cast<uint32_t*>(g_xq) + row * (DIM / 4);
#pragma unroll
    for (int q = 0; q < 4; ++q)
        out32[lane + 32 * q] =
            pack4s8(__float2int_rn(v[q].x * inv), __float2int_rn(v[q].y * inv),
                    __float2int_rn(v[q].z * inv), __float2int_rn(v[q].w * inv));

    if (lane == 0) {
        g_scale[row] = m * (1.0f / 127.0f);
        g_pack[row]  = 0ull;     // key=0 < any real key
        if (row == 0) g_cnt = 0;
    }
}

// ---------------------------------------------------------------------------
// Kernel 1: symmetric (triangular) int8 mma.sync GEMM + dual-sided argmax.
// 148 CTAs x 256 threads, 2x4 warp grid, 64x32 warp tile, batched fragments.
// Column-side fold uses the packed 32-bit (truncated-key | 127-localrow)
// shfl+umax reduction.
// ---------------------------------------------------------------------------
__global__ __launch_bounds__(256, 1) void gemm_argmax_kernel() {
    extern __shared__ __align__(128) char smem[];
    const uint32_t sb = smem_u32(smem);

    const int tid  = threadIdx.x;
    const int wid  = tid >> 5;
    const int lane = tid & 31;
    const int wr   = wid >> 2;           // warp row (0-1) -> 64 rows
    const int wc   = wid & 3;            // warp col (0-3) -> 32 cols

    const int t_begin = (int)((long long)blockIdx.x * NTILES / NCTA);
    const int t_end   = (int)((long long)(blockIdx.x + 1) * NTILES / NCTA);

    const uint8_t* xq = g_xq;

    const int a_row_lo = ((lane >> 3) & 1) * 8 + (lane & 7);
    const int a_kext   = (lane >> 4) * 16;
    const int b_row_lo = ((lane >> 4) & 1) * 8 + (lane & 7);
    const int b_kext   = ((lane >> 3) & 1) * 16;

    float* sV = reinterpret_cast<float*>(smem + SMO_B);          // scratch [128][4]
    int*   sI = reinterpret_cast<int*>(smem + SMO_B + 2048);

    int t = t_begin;
    while (t < t_end) {
        int strip, d0;
        strip_of(t, strip, d0);
        const int seg_end = min(t_end, strip_end(strip));
        const int NC   = (seg_end - t) * KCH;
        const int m0   = strip * BM;

        // per-segment row scales (candidate-side factor for the column fold)
        float srow[8];
#pragma unroll
        for (int mt = 0; mt < 4; ++mt) {
            const int r0 = m0 + wr * 64 + mt * 16 + (lane >> 2);
            srow[mt * 2]     = g_scale[r0];
            srow[mt * 2 + 1] = g_scale[r0 + 8];
        }

        __syncthreads();   // prior segment fully consumed A & B & scratch

        // ---- A strip: 4 chunks of [128 x 128] int8, SW128 (one group)
#pragma unroll
        for (int kc = 0; kc < KCH; ++kc) {
#pragma unroll
            for (int i = 0; i < 4; ++i) {
                const int u   = i * 256 + tid;       // 16B units
                const int row = u >> 3;
                const int c16 = u & 7;
                cp16(sb + SMO_A + kc * CHB + sw128(row * 128 + c16 * 16),
                     xq + (size_t)(m0 + row) * DIM + kc * KCB + c16 * 16);
            }
        }
        CP_COMMIT();

        // ---- B prologue: chunks 0..2 into slots 0..2
#pragma unroll
        for (int p = 0; p < 3; ++p) {
            const int j  = (strip + d0) & (NSTRIP - 1);  // p<4 -> tile 0
            const int kc = p;
            const int n0 = j * BN;
#pragma unroll
            for (int i = 0; i < 4; ++i) {
                const int u   = i * 256 + tid;
                const int row = u >> 3;
                const int c16 = u & 7;
                cp16(sb + SMO_B + p * CHB + sw128(row * 128 + c16 * 16),
                     xq + (size_t)(n0 + row) * DIM + kc * KCB + c16 * 16);
            }
            CP_COMMIT();
        }
        CP_WAIT(3);          // A landed
        __syncthreads();

        int acc[4][4][4];
#pragma unroll
        for (int mt = 0; mt < 4; ++mt)
#pragma unroll
            for (int nt = 0; nt < 4; ++nt)
#pragma unroll
                for (int k = 0; k < 4; ++k) acc[mt][nt][k] = 0;

        float bestV[8];
        int   bestI[8];
#pragma unroll
        for (int i = 0; i < 8; ++i) { bestV[i] = -3.402823466e38f; bestI[i] = 0; }

        for (int g = 0; g < NC; ++g) {
            CP_WAIT(2);
            __syncthreads();

            const int gn = g + 3;
            if (gn < NC) {
                const int j  = (strip + d0 + (gn >> 2)) & (NSTRIP - 1);
                const int kc = gn & 3;
                const int n0 = j * BN;
                const uint32_t dst = sb + SMO_B + (gn & 3) * CHB;
#pragma unroll
                for (int i = 0; i < 4; ++i) {
                    const int u   = i * 256 + tid;
                    const int row = u >> 3;
                    const int c16 = u & 7;
                    cp16(dst + sw128(row * 128 + c16 * 16),
                         xq + (size_t)(n0 + row) * DIM + kc * KCB + c16 * 16);
                }
            }
            CP_COMMIT();

            // ---- compute chunk g: batch ALL fragments, then 64 mma
            const uint32_t abase = sb + SMO_A + (g & 3) * CHB;
            const uint32_t bbase = sb + SMO_B + (g & 3) * CHB;
            uint32_t afr[4][4][4];    // [ks][mt][4]
            uint32_t bfr[4][2][4];    // [ks][h][4]
#pragma unroll
            for (int ks = 0; ks < 4; ++ks) {
#pragma unroll
                for (int mt = 0; mt < 4; ++mt) {
                    const int row = wr * 64 + mt * 16 + a_row_lo;
                    ldsm4(afr[ks][mt], abase + sw128(row * 128 + ks * 32 + a_kext));
                }
#pragma unroll
                for (int h2 = 0; h2 < 2; ++h2) {
                    const int row = wc * 32 + h2 * 16 + b_row_lo;
                    ldsm4(bfr[ks][h2], bbase + sw128(row * 128 + ks * 32 + b_kext));
                }
            }
#pragma unroll
            for (int ks = 0; ks < 4; ++ks)
#pragma unroll
                for (int mt = 0; mt < 4; ++mt)
#pragma unroll
                    for (int nt = 0; nt < 4; ++nt)
                        mma16832s8(acc[mt][nt], afr[ks][mt],
                                   &bfr[ks][nt >> 1][(nt & 1) * 2]);

            // ---- tile finished (K=512): dual-sided fold, reset acc
            if ((g & 3) == 3) {
                const int d    = d0 + (g >> 2);
                const int j    = (strip + d) & (NSTRIP - 1);
                const int nc0  = j * BN + wc * 32;
                const bool diag = (d == 0);

                float scs[8];
#pragma unroll
                for (int nt = 0; nt < 4; ++nt) {
                    const int c0 = nc0 + nt * 8 + (lane & 3) * 2;
                    scs[nt * 2]     = g_scale[c0];
                    scs[nt * 2 + 1] = g_scale[c0 + 1];
                }

                // row side: v = s_col * dot (missing s_row constant per slot)
#pragma unroll
                for (int mt = 0; mt < 4; ++mt) {
                    const int row0 = m0 + wr * 64 + mt * 16 + (lane >> 2);
                    const int row1 = row0 + 8;
#pragma unroll
                    for (int nt = 0; nt < 4; ++nt) {
                        const int c0 = nc0 + nt * 8 + (lane & 3) * 2;
                        const float v00 = (float)acc[mt][nt][0] * scs[nt * 2];
                        const float v01 = (float)acc[mt][nt][1] * scs[nt * 2 + 1];
                        const float v10 = (float)acc[mt][nt][2] * scs[nt * 2];
                        const float v11 = (float)acc[mt][nt][3] * scs[nt * 2 + 1];
                        const int b0 = mt * 2, b1 = mt * 2 + 1;
                        if (c0 != row0 && v00 > bestV[b0]) { bestV[b0] = v00; bestI[b0] = c0; }
                        if (c0 + 1 != row0 && v01 > bestV[b0]) { bestV[b0] = v01; bestI[b0] = c0 + 1; }
                        if (c0 != row1 && v10 > bestV[b1]) { bestV[b1] = v10; bestI[b1] = c0; }
                        if (c0 + 1 != row1 && v11 > bestV[b1]) { bestV[b1] = v11; bestI[b1] = c0 + 1; }
                    }
                }

                // column side: v = s_row * dot, skipped for diagonal tile.
                // Packed 32-bit (truncated key | 127-localrow) shfl+umax.
                if (!diag) {
                    float cV[8];
                    int   cL[8];   // local row within strip (0..127)
#pragma unroll
                    for (int k = 0; k < 8; ++k) { cV[k] = -3.402823466e38f; cL[k] = 0; }
#pragma unroll
                    for (int mt = 0; mt < 4; ++mt) {
                        const int l0 = wr * 64 + mt * 16 + (lane >> 2);
                        const int l1 = l0 + 8;
                        const float s0 = srow[mt * 2], s1 = srow[mt * 2 + 1];
#pragma unroll
                        for (int nt = 0; nt < 4; ++nt) {
                            const int k0 = nt * 2, k1 = nt * 2 + 1;
                            const float v00 = (float)acc[mt][nt][0] * s0;
                            const float v01 = (float)acc[mt][nt][1] * s0;
                            const float v10 = (float)acc[mt][nt][2] * s1;
                            const float v11 = (float)acc[mt][nt][3] * s1;
                            if (v00 > cV[k0]) { cV[k0] = v00; cL[k0] = l0; }
                            if (v10 > cV[k0]) { cV[k0] = v10; cL[k0] = l1; }
                            if (v01 > cV[k1]) { cV[k1] = v01; cL[k1] = l0; }
                            if (v11 > cV[k1]) { cV[k1] = v11; cL[k1] = l1; }
                        }
                    }
#pragma unroll
                    for (int k = 0; k < 8; ++k) {
                        // packed: truncated monotone key (top 25b) | 127-lrow
                        uint32_t pk = (fkey(cV[k]) & 0xFFFFFF80u)
                                      | (uint32_t)(127 - cL[k]);
#pragma unroll
                        for (int o = 4; o <= 16; o <<= 1)
                            pk = max(pk, __shfl_xor_sync(0xffffffffu, pk, o));
                        if ((lane >> 2) == 0) {
                            const int lrow = 127 - (int)(pk & 0x7F);
                            const int col  = nc0 + (k >> 1) * 8 + (lane & 3) * 2 + (k & 1);
                            const unsigned long long pk64 =
                                ((unsigned long long)(pk & 0xFFFFFF80u) << 32) |
                                (uint32_t)(0x7FFFFFFFu - (m0 + lrow));
                            atomicMax(&g_pack[col], pk64);
                        }
                    }
                }

#pragma unroll
                for (int mt = 0; mt < 4; ++mt)
#pragma unroll
                    for (int nt = 0; nt < 4; ++nt) {
                        acc[mt][nt][0] = 0; acc[mt][nt][1] = 0;
                        acc[mt][nt][2] = 0; acc[mt][nt][3] = 0;
                    }
            }
        }

        // ---- flush row-side bests for this strip segment
        __syncthreads();   // ring quiescent -> reuse as scratch
#pragma unroll
        for (int b = 0; b < 8; ++b) {
            float v = bestV[b];
            int   i = bestI[b];
#pragma unroll
            for (int o = 2; o > 0; o >>= 1) {
                const float ov = __shfl_xor_sync(0xffffffffu, v, o);
                const int   oi = __shfl_xor_sync(0xffffffffu, i, o);
                if (ov > v || (ov == v && oi < i)) { v = ov; i = oi; }
            }
            if ((lane & 3) == 0) {
                const int lrow = wr * 64 + (b >> 1) * 16 + (b & 1) * 8 + (lane >> 2);
                sV[lrow * 4 + wc] = v;
                sI[lrow * 4 + wc] = i;
            }
        }
        __syncthreads();
        if (tid < BM) {
            float v = sV[tid * 4];
            int   i = sI[tid * 4];
#pragma unroll
            for (int q = 1; q < 4; ++q) {
                const float ov = sV[tid * 4 + q];
                const int   oi = sI[tid * 4 + q];
                if (ov > v || (ov == v && oi < i)) { v = ov; i = oi; }
            }
            atom_pack_max(&g_pack[m0 + tid], v, i);
        }

        t = seg_end;
    }
}

// ---------------------------------------------------------------------------
// Kernel 2: rho (exact fp32), warp-per-row + block-level fused loss.
// ---------------------------------------------------------------------------
__global__ __launch_bounds__(256) void rho_loss_kernel(const float* __restrict__ x,
                                                       float* __restrict__ out) {
    const int warp = threadIdx.x >> 5;
    const int lane = threadIdx.x & 31;
    const int row  = blockIdx.x * 8 + warp;

    const unsigned long long p = g_pack[row];
    const int nn = 0x7FFFFFFF - (int)(uint32_t)(p & 0xFFFFFFFFull);

    const float4* ra = reinterpret_cast<const float4*>(x + (size_t)row * DIM);
    const float4* rb = reinterpret_cast<const float4*>(x + (size_t)nn  * DIM);
    float s = 0.0f;
#pragma unroll
    for (int q = 0; q < 4; ++q) {
        const float4 a = ra[lane + 32 * q];
        const float4 b = rb[lane + 32 * q];
        const float dx = a.x - b.x + 1e-6f;
        const float dy = a.y - b.y + 1e-6f;
        const float dz = a.z - b.z + 1e-6f;
        const float dw = a.w - b.w + 1e-6f;
        s += dx * dx + dy * dy + dz * dz + dw * dw;
    }
#pragma unroll
    for (int o = 16; o > 0; o >>= 1) s += __shfl_xor_sync(0xffffffffu, s, o);

    if (lane == 0) g_term[row] = logf(sqrtf(s) + 1e-8f);

    __shared__ int slast;
    __shared__ float ws[8];
    __threadfence();
    __syncthreads();
    if (threadIdx.x == 0) {
        const int old = atomicAdd(&g_cnt, 8);
        slast = (old == NROW - 8);
    }
    __syncthreads();

    if (slast) {   // last block: deterministic fixed-order global reduction
        __threadfence();
        float acc = 0.0f;
        for (int i = threadIdx.x; i < NROW; i += 256) acc += g_term[i];
#pragma unroll
        for (int o = 16; o > 0; o >>= 1) acc += __shfl_xor_sync(0xffffffffu, acc, o);
        if (lane == 0) ws[warp] = acc;
        __syncthreads();
        if (threadIdx.x == 0) {
            float tot = 0.0f;
#pragma unroll
            for (int w = 0; w < 8; ++w) tot += ws[w];
            out[0] = -tot / (float)NROW;
        }
    }
}

extern "C" void kernel_launch(void* const* d_in, const int* in_sizes, int n_in,
                              void* d_out, int out_size) {
    (void)in_sizes; (void)n_in; (void)out_size;
    const float* x = (const float*)d_in[0];
    float* out = (float*)d_out;

    cudaFuncSetAttribute(gemm_argmax_kernel,
                         cudaFuncAttributeMaxDynamicSharedMemorySize, SMEM_SZ);

    quant_kernel<<<NROW / 8, 256>>>(x);
    gemm_argmax_kernel<<<NCTA, 256, SMEM_SZ>>>();
    rho_loss_kernel<<<NROW / 8, 256>>>(x, out);
}

// round 15
// speedup vs baseline: 1.2233x; 1.0486x over previous
#include <cuda_runtime.h>
#include <math.h>
#include <stdint.h>

// ---------------------------------------------------------------------------
// Problem constants (x: [8192, 512] fp32)
// ---------------------------------------------------------------------------
constexpr int NROW = 8192;
constexpr int DIM  = 512;

constexpr int BM   = 128;           // rows per strip
constexpr int BN   = 128;           // cols per tile
constexpr int NSTRIP = NROW / BM;   // 64 strips
constexpr int CHB16 = BM * 128;     // 16384 B per 16KB chunk (K=128 int8)
constexpr int SUPB  = 2 * CHB16;    // 32768 B super-chunk (K=256)
constexpr int NTILES = 33 * 32 + 32 * 32;   // 2080
constexpr int NCTA   = 148;

constexpr int SMO_A = 0;                       // 4 * 16KB resident A strip
constexpr int SMO_B = 4 * CHB16;               // 4-slot super ring (4 * 32KB)
constexpr int SMEM_SZ = SMO_B + 4 * SUPB;      // 196608 B

// Scratch (no allocations allowed anywhere)
__device__ uint8_t g_xq[NROW * DIM];           // int8 quantized x
__device__ float   g_scale[NROW];              // per-row dequant scale
__device__ unsigned long long g_pack[NROW];    // packed (valkey<<32)|(0x7FFFFFFF-idx)
__device__ float g_term[NROW];
__device__ int   g_cnt;

// ---------------------------------------------------------------------------
// PTX helpers (compute_100-safe: cp.async / ldmatrix / mma.sync / redux)
// ---------------------------------------------------------------------------
__device__ __forceinline__ uint32_t smem_u32(const void* p) {
    uint32_t a;
    asm("{ .reg .u64 t; cvta.to.shared.u64 t, %1; cvt.u32.u64 %0, t; }"
        : "=r"(a) : "l"(p));
    return a;
}
__device__ __forceinline__ void cp16(uint32_t s, const void* g) {
    asm volatile("cp.async.cg.shared.global [%0], [%1], 16;" :: "r"(s), "l"(g));
}
#define CP_COMMIT() asm volatile("cp.async.commit_group;" ::: "memory")
#define CP_WAIT(n)  asm volatile("cp.async.wait_group %0;" :: "n"(n) : "memory")

__device__ __forceinline__ uint32_t sw128(uint32_t off) {
    return off ^ ((off >> 3) & 0x70);
}
__device__ __forceinline__ void ldsm4(uint32_t* r, uint32_t addr) {
    asm volatile("ldmatrix.sync.aligned.m8n8.x4.shared.b16 {%0,%1,%2,%3}, [%4];"
                 : "=r"(r[0]), "=r"(r[1]), "=r"(r[2]), "=r"(r[3]) : "r"(addr));
}
__device__ __forceinline__ void mma16832s8(int* d, const uint32_t* a, const uint32_t* b) {
    asm volatile(
        "mma.sync.aligned.m16n8k32.row.col.s32.s8.s8.s32 "
        "{%0,%1,%2,%3}, {%4,%5,%6,%7}, {%8,%9}, {%0,%1,%2,%3};"
        : "+r"(d[0]), "+r"(d[1]), "+r"(d[2]), "+r"(d[3])
        : "r"(a[0]), "r"(a[1]), "r"(a[2]), "r"(a[3]), "r"(b[0]), "r"(b[1]));
}

// saturating s8 pack: d = q0 | q1<<8 | q2<<16 | q3<<24
__device__ __forceinline__ uint32_t pack4s8(int q0, int q1, int q2, int q3) {
    uint32_t t, d;
    asm("cvt.pack.sat.s8.s32.b32 %0, %1, %2, %3;" : "=r"(t) : "r"(q3), "r"(q2), "r"(0));
    asm("cvt.pack.sat.s8.s32.b32 %0, %1, %2, %3;" : "=r"(d) : "r"(q1), "r"(q0), "r"(t));
    return d;
}

// Monotone u32 key for float ordering: larger float -> larger key.
__device__ __forceinline__ uint32_t fkey(float v) {
    const uint32_t b = __float_as_uint(v);
    return (b & 0x80000000u) ? ~b : (b | 0x80000000u);
}

// Monotone packed argmax key: larger value -> larger pack; equal value ->
// smaller index -> larger pack (first-index tie-break).
__device__ __forceinline__ void atom_pack_max(unsigned long long* p, float v, int idx) {
    const unsigned long long pk =
        ((unsigned long long)fkey(v) << 32) | (uint32_t)(0x7FFFFFFFu - idx);
    atomicMax(p, pk);
}

// strip-major flattened tile list helpers
__device__ __forceinline__ void strip_of(int t, int& i, int& d) {
    if (t < 33 * 32) { i = t / 33; d = t - i * 33; }
    else { const int u = t - 33 * 32; i = 32 + u / 32; d = u & 31; }
}
__device__ __forceinline__ int strip_end(int i) {
    return (i < 32) ? (i + 1) * 33 : 33 * 32 + (i - 31) * 32;
}

// ---------------------------------------------------------------------------
// Kernel 0: per-row int8 quantization, warp-per-row, fully coalesced.
// ---------------------------------------------------------------------------
__global__ __launch_bounds__(256) void quant_kernel(const float* __restrict__ x) {
    const int warp = threadIdx.x >> 5;
    const int lane = threadIdx.x & 31;
    const int row  = blockIdx.x * 8 + warp;

    const float4* rp = reinterpret_cast<const float4*>(x + (size_t)row * DIM);
    float4 v[4];
#pragma unroll
    for (int q = 0; q < 4; ++q) v[q] = rp[lane + 32 * q];

    uint32_t mb = 0;
#pragma unroll
    for (int q = 0; q < 4; ++q) {
        mb = max(mb, __float_as_uint(fabsf(v[q].x)));
        mb = max(mb, __float_as_uint(fabsf(v[q].y)));
        mb = max(mb, __float_as_uint(fabsf(v[q].z)));
        mb = max(mb, __float_as_uint(fabsf(v[q].w)));
    }
    const float m   = __uint_as_float(__reduce_max_sync(0xffffffffu, mb));
    const float inv = 127.0f / m;

    uint32_t* out32 = reinterpret_cast<uint32_t*>(g_xq) + row * (DIM / 4);
#pragma unroll
    for (int q = 0; q < 4; ++q)
        out32[lane + 32 * q] =
            pack4s8(__float2int_rn(v[q].x * inv), __float2int_rn(v[q].y * inv),
                    __float2int_rn(v[q].z * inv), __float2int_rn(v[q].w * inv));

    if (lane == 0) {
        g_scale[row] = m * (1.0f / 127.0f);
        g_pack[row]  = 0ull;     // key=0 < any real key
        if (row == 0) g_cnt = 0;
    }
}

// ---------------------------------------------------------------------------
// Kernel 1: symmetric (triangular) int8 mma.sync GEMM + dual-sided argmax.
// 148 CTAs x 256 threads, 2x4 warp grid, 64x32 warp tile.
// Pipeline granularity = 32KB super-chunks (2 x 16KB chunks): one
// CP_WAIT + __syncthreads + commit per super-chunk (half the sync cadence).
// Inner 16KB compute block (batched 24 ldsm + 64 mma) unchanged.
// ---------------------------------------------------------------------------
__global__ __launch_bounds__(256, 1) void gemm_argmax_kernel() {
    extern __shared__ __align__(128) char smem[];
    const uint32_t sb = smem_u32(smem);

    const int tid  = threadIdx.x;
    const int wid  = tid >> 5;
    const int lane = tid & 31;
    const int wr   = wid >> 2;           // warp row (0-1) -> 64 rows
    const int wc   = wid & 3;            // warp col (0-3) -> 32 cols

    const int t_begin = (int)((long long)blockIdx.x * NTILES / NCTA);
    const int t_end   = (int)((long long)(blockIdx.x + 1) * NTILES / NCTA);

    const uint8_t* xq = g_xq;

    const int a_row_lo = ((lane >> 3) & 1) * 8 + (lane & 7);
    const int a_kext   = (lane >> 4) * 16;
    const int b_row_lo = ((lane >> 4) & 1) * 8 + (lane & 7);
    const int b_kext   = ((lane >> 3) & 1) * 16;

    float* sV = reinterpret_cast<float*>(smem + SMO_B);          // scratch [128][4]
    int*   sI = reinterpret_cast<int*>(smem + SMO_B + 2048);

    int t = t_begin;
    while (t < t_end) {
        int strip, d0;
        strip_of(t, strip, d0);
        const int seg_end = min(t_end, strip_end(strip));
        const int NSUP = (seg_end - t) * 2;   // 2 super-chunks per tile
        const int m0   = strip * BM;

        // per-segment row scales (candidate-side factor for the column fold)
        float srow[8];
#pragma unroll
        for (int mt = 0; mt < 4; ++mt) {
            const int r0 = m0 + wr * 64 + mt * 16 + (lane >> 2);
            srow[mt * 2]     = g_scale[r0];
            srow[mt * 2 + 1] = g_scale[r0 + 8];
        }

        __syncthreads();   // prior segment fully consumed A & B & scratch

        // ---- A strip: 4 chunks of [128 x 128] int8, SW128 (one group)
#pragma unroll
        for (int i = 0; i < 16; ++i) {
            const int u   = i * 256 + tid;       // 0..4095 16B units
            const int kc  = u >> 10;
            const int w   = u & 1023;
            const int row = w >> 3;
            const int c16 = w & 7;
            cp16(sb + SMO_A + kc * CHB16 + sw128(row * 128 + c16 * 16),
                 xq + (size_t)(m0 + row) * DIM + kc * 128 + c16 * 16);
        }
        CP_COMMIT();

        // ---- B prologue: super-chunks 0..2 into super-slots 0..2
#pragma unroll
        for (int p = 0; p < 3; ++p) {
            const int j  = (strip + d0 + (p >> 1)) & (NSTRIP - 1);
            const int n0 = j * BN;
#pragma unroll
            for (int i = 0; i < 8; ++i) {
                const int u   = i * 256 + tid;   // 0..2047 16B units
                const int ch  = u >> 10;
                const int w   = u & 1023;
                const int row = w >> 3;
                const int c16 = w & 7;
                const int kc  = (p & 1) * 2 + ch;
                cp16(sb + SMO_B + p * SUPB + ch * CHB16 + sw128(row * 128 + c16 * 16),
                     xq + (size_t)(n0 + row) * DIM + kc * 128 + c16 * 16);
            }
            CP_COMMIT();
        }
        CP_WAIT(3);          // A landed
        __syncthreads();

        int acc[4][4][4];
#pragma unroll
        for (int mt = 0; mt < 4; ++mt)
#pragma unroll
            for (int nt = 0; nt < 4; ++nt)
#pragma unroll
                for (int k = 0; k < 4; ++k) acc[mt][nt][k] = 0;

        float bestV[8];
        int   bestI[8];
#pragma unroll
        for (int i = 0; i < 8; ++i) { bestV[i] = -3.402823466e38f; bestI[i] = 0; }

        for (int g = 0; g < NSUP; ++g) {
            CP_WAIT(2);
            __syncthreads();

            const int gn = g + 3;
            if (gn < NSUP) {
                const int j  = (strip + d0 + (gn >> 1)) & (NSTRIP - 1);
                const int n0 = j * BN;
                const uint32_t dst = sb + SMO_B + (gn & 3) * SUPB;
#pragma unroll
                for (int i = 0; i < 8; ++i) {
                    const int u   = i * 256 + tid;
                    const int ch  = u >> 10;
                    const int w   = u & 1023;
                    const int row = w >> 3;
                    const int c16 = w & 7;
                    const int kc  = (gn & 1) * 2 + ch;
                    cp16(dst + ch * CHB16 + sw128(row * 128 + c16 * 16),
                         xq + (size_t)(n0 + row) * DIM + kc * 128 + c16 * 16);
                }
            }
            CP_COMMIT();

            // ---- compute 2 chunks of this super-chunk
#pragma unroll
            for (int sub = 0; sub < 2; ++sub) {
                const uint32_t abase = sb + SMO_A + ((g & 1) * 2 + sub) * CHB16;
                const uint32_t bbase = sb + SMO_B + (g & 3) * SUPB + sub * CHB16;
                uint32_t afr[4][4][4];    // [ks][mt][4]
                uint32_t bfr[4][2][4];    // [ks][h][4]
#pragma unroll
                for (int ks = 0; ks < 4; ++ks) {
#pragma unroll
                    for (int mt = 0; mt < 4; ++mt) {
                        const int row = wr * 64 + mt * 16 + a_row_lo;
                        ldsm4(afr[ks][mt], abase + sw128(row * 128 + ks * 32 + a_kext));
                    }
#pragma unroll
                    for (int h2 = 0; h2 < 2; ++h2) {
                        const int row = wc * 32 + h2 * 16 + b_row_lo;
                        ldsm4(bfr[ks][h2], bbase + sw128(row * 128 + ks * 32 + b_kext));
                    }
                }
#pragma unroll
                for (int ks = 0; ks < 4; ++ks)
#pragma unroll
                    for (int mt = 0; mt < 4; ++mt)
#pragma unroll
                        for (int nt = 0; nt < 4; ++nt)
                            mma16832s8(acc[mt][nt], afr[ks][mt],
                                       &bfr[ks][nt >> 1][(nt & 1) * 2]);
            }

            // ---- tile finished (odd super-chunk): dual-sided fold, reset
            if (g & 1) {
                const int d    = d0 + (g >> 1);
                const int j    = (strip + d) & (NSTRIP - 1);
                const int nc0  = j * BN + wc * 32;
                const bool diag = (d == 0);

                float scs[8];
#pragma unroll
                for (int nt = 0; nt < 4; ++nt) {
                    const int c0 = nc0 + nt * 8 + (lane & 3) * 2;
                    scs[nt * 2]     = g_scale[c0];
                    scs[nt * 2 + 1] = g_scale[c0 + 1];
                }

                // row side: v = s_col * dot (missing s_row constant per slot)
#pragma unroll
                for (int mt = 0; mt < 4; ++mt) {
                    const int row0 = m0 + wr * 64 + mt * 16 + (lane >> 2);
                    const int row1 = row0 + 8;
#pragma unroll
                    for (int nt = 0; nt < 4; ++nt) {
                        const int c0 = nc0 + nt * 8 + (lane & 3) * 2;
                        const float v00 = (float)acc[mt][nt][0] * scs[nt * 2];
                        const float v01 = (float)acc[mt][nt][1] * scs[nt * 2 + 1];
                        const float v10 = (float)acc[mt][nt][2] * scs[nt * 2];
                        const float v11 = (float)acc[mt][nt][3] * scs[nt * 2 + 1];
                        const int b0 = mt * 2, b1 = mt * 2 + 1;
                        if (c0 != row0 && v00 > bestV[b0]) { bestV[b0] = v00; bestI[b0] = c0; }
                        if (c0 + 1 != row0 && v01 > bestV[b0]) { bestV[b0] = v01; bestI[b0] = c0 + 1; }
                        if (c0 != row1 && v10 > bestV[b1]) { bestV[b1] = v10; bestI[b1] = c0; }
                        if (c0 + 1 != row1 && v11 > bestV[b1]) { bestV[b1] = v11; bestI[b1] = c0 + 1; }
                    }
                }

                // column side: v = s_row * dot, skipped for diagonal tile.
                // Packed 32-bit (truncated key | 127-localrow) shfl+umax.
                if (!diag) {
                    float cV[8];
                    int   cL[8];   // local row within strip (0..127)
#pragma unroll
                    for (int k = 0; k < 8; ++k) { cV[k] = -3.402823466e38f; cL[k] = 0; }
#pragma unroll
                    for (int mt = 0; mt < 4; ++mt) {
                        const int l0 = wr * 64 + mt * 16 + (lane >> 2);
                        const int l1 = l0 + 8;
                        const float s0 = srow[mt * 2], s1 = srow[mt * 2 + 1];
#pragma unroll
                        for (int nt = 0; nt < 4; ++nt) {
                            const int k0 = nt * 2, k1 = nt * 2 + 1;
                            const float v00 = (float)acc[mt][nt][0] * s0;
                            const float v01 = (float)acc[mt][nt][1] * s0;
                            const float v10 = (float)acc[mt][nt][2] * s1;
                            const float v11 = (float)acc[mt][nt][3] * s1;
                            if (v00 > cV[k0]) { cV[k0] = v00; cL[k0] = l0; }
                            if (v10 > cV[k0]) { cV[k0] = v10; cL[k0] = l1; }
                            if (v01 > cV[k1]) { cV[k1] = v01; cL[k1] = l0; }
                            if (v11 > cV[k1]) { cV[k1] = v11; cL[k1] = l1; }
                        }
                    }
#pragma unroll
                    for (int k = 0; k < 8; ++k) {
                        // packed: truncated monotone key (top 25b) | 127-lrow
                        uint32_t pk = (fkey(cV[k]) & 0xFFFFFF80u)
                                      | (uint32_t)(127 - cL[k]);
#pragma unroll
                        for (int o = 4; o <= 16; o <<= 1)
                            pk = max(pk, __shfl_xor_sync(0xffffffffu, pk, o));
                        if ((lane >> 2) == 0) {
                            const int lrow = 127 - (int)(pk & 0x7F);
                            const int col  = nc0 + (k >> 1) * 8 + (lane & 3) * 2 + (k & 1);
                            const unsigned long long pk64 =
                                ((unsigned long long)(pk & 0xFFFFFF80u) << 32) |
                                (uint32_t)(0x7FFFFFFFu - (m0 + lrow));
                            atomicMax(&g_pack[col], pk64);
                        }
                    }
                }

#pragma unroll
                for (int mt = 0; mt < 4; ++mt)
#pragma unroll
                    for (int nt = 0; nt < 4; ++nt) {
                        acc[mt][nt][0] = 0; acc[mt][nt][1] = 0;
                        acc[mt][nt][2] = 0; acc[mt][nt][3] = 0;
                    }
            }
        }

        // ---- flush row-side bests for this strip segment
        __syncthreads();   // ring quiescent -> reuse as scratch
#pragma unroll
        for (int b = 0; b < 8; ++b) {
            float v = bestV[b];
            int   i = bestI[b];
#pragma unroll
            for (int o = 2; o > 0; o >>= 1) {
                const float ov = __shfl_xor_sync(0xffffffffu, v, o);
                const int   oi = __shfl_xor_sync(0xffffffffu, i, o);
                if (ov > v || (ov == v && oi < i)) { v = ov; i = oi; }
            }
            if ((lane & 3) == 0) {
                const int lrow = wr * 64 + (b >> 1) * 16 + (b & 1) * 8 + (lane >> 2);
                sV[lrow * 4 + wc] = v;
                sI[lrow * 4 + wc] = i;
            }
        }
        __syncthreads();
        if (tid < BM) {
            float v = sV[tid * 4];
            int   i = sI[tid * 4];
#pragma unroll
            for (int q = 1; q < 4; ++q) {
                const float ov = sV[tid * 4 + q];
                const int   oi = sI[tid * 4 + q];
                if (ov > v || (ov == v && oi < i)) { v = ov; i = oi; }
            }
            atom_pack_max(&g_pack[m0 + tid], v, i);
        }

        t = seg_end;
    }
}

// ---------------------------------------------------------------------------
// Kernel 2: rho (exact fp32), warp-per-row + block-level fused loss.
// ---------------------------------------------------------------------------
__global__ __launch_bounds__(256) void rho_loss_kernel(const float* __restrict__ x,
                                                       float* __restrict__ out) {
    const int warp = threadIdx.x >> 5;
    const int lane = threadIdx.x & 31;
    const int row  = blockIdx.x * 8 + warp;

    const unsigned long long p = g_pack[row];
    const int nn = 0x7FFFFFFF - (int)(uint32_t)(p & 0xFFFFFFFFull);

    const float4* ra = reinterpret_cast<const float4*>(x + (size_t)row * DIM);
    const float4* rb = reinterpret_cast<const float4*>(x + (size_t)nn  * DIM);
    float s = 0.0f;
#pragma unroll
    for (int q = 0; q < 4; ++q) {
        const float4 a = ra[lane + 32 * q];
        const float4 b = rb[lane + 32 * q];
        const float dx = a.x - b.x + 1e-6f;
        const float dy = a.y - b.y + 1e-6f;
        const float dz = a.z - b.z + 1e-6f;
        const float dw = a.w - b.w + 1e-6f;
        s += dx * dx + dy * dy + dz * dz + dw * dw;
    }
#pragma unroll
    for (int o = 16; o > 0; o >>= 1) s += __shfl_xor_sync(0xffffffffu, s, o);

    if (lane == 0) g_term[row] = logf(sqrtf(s) + 1e-8f);

    __shared__ int slast;
    __shared__ float ws[8];
    __threadfence();
    __syncthreads();
    if (threadIdx.x == 0) {
        const int old = atomicAdd(&g_cnt, 8);
        slast = (old == NROW - 8);
    }
    __syncthreads();

    if (slast) {   // last block: deterministic fixed-order global reduction
        __threadfence();
        float acc = 0.0f;
        for (int i = threadIdx.x; i < NROW; i += 256) acc += g_term[i];
#pragma unroll
        for (int o = 16; o > 0; o >>= 1) acc += __shfl_xor_sync(0xffffffffu, acc, o);
        if (lane == 0) ws[warp] = acc;
        __syncthreads();
        if (threadIdx.x == 0) {
            float tot = 0.0f;
#pragma unroll
            for (int w = 0; w < 8; ++w) tot += ws[w];
            out[0] = -tot / (float)NROW;
        }
    }
}

extern "C" void kernel_launch(void* const* d_in, const int* in_sizes, int n_in,
                              void* d_out, int out_size) {
    (void)in_sizes; (void)n_in; (void)out_size;
    const float* x = (const float*)d_in[0];
    float* out = (float*)d_out;

    cudaFuncSetAttribute(gemm_argmax_kernel,
                         cudaFuncAttributeMaxDynamicSharedMemorySize, SMEM_SZ);

    quant_kernel<<<NROW / 8, 256>>>(x);
    gemm_argmax_kernel<<<NCTA, 256, SMEM_SZ>>>();
    rho_loss_kernel<<<NROW / 8, 256>>>(x, out);
}

// round 16
// speedup vs baseline: 1.2307x; 1.0060x over previous
#include <cuda_runtime.h>
#include <math.h>
#include <stdint.h>

// ---------------------------------------------------------------------------
// Problem constants (x: [8192, 512] fp32)
// ---------------------------------------------------------------------------
constexpr int NROW = 8192;
constexpr int DIM  = 512;

constexpr int BM   = 128;           // rows per strip
constexpr int BN   = 128;           // cols per tile
constexpr int NSTRIP = NROW / BM;   // 64 strips
constexpr int CHB16 = BM * 128;     // 16384 B per 16KB chunk (K=128 int8)
constexpr int SUPB  = 2 * CHB16;    // 32768 B super-chunk (K=256)
constexpr int NTILES = 33 * 32 + 32 * 32;   // 2080
constexpr int NCTA   = 148;

constexpr int SMO_A = 0;                       // 4 * 16KB resident A strip
constexpr int SMO_B = 4 * CHB16;               // 4-slot super ring (4 * 32KB)
constexpr int SMEM_SZ = SMO_B + 4 * SUPB;      // 196608 B

// Scratch (no allocations allowed anywhere)
__device__ uint8_t g_xq[NROW * DIM];           // int8 quantized x
__device__ float   g_scale[NROW];              // per-row dequant scale
__device__ unsigned long long g_pack[NROW];    // packed (valkey<<32)|(0x7FFFFFFF-idx)
__device__ float g_term[NROW];
__device__ int   g_cnt;

// ---------------------------------------------------------------------------
// PTX helpers (compute_100-safe: cp.async / ldmatrix / mma.sync / redux)
// ---------------------------------------------------------------------------
__device__ __forceinline__ uint32_t smem_u32(const void* p) {
    uint32_t a;
    asm("{ .reg .u64 t; cvta.to.shared.u64 t, %1; cvt.u32.u64 %0, t; }"
        : "=r"(a) : "l"(p));
    return a;
}
__device__ __forceinline__ void cp16(uint32_t s, const void* g) {
    asm volatile("cp.async.cg.shared.global [%0], [%1], 16;" :: "r"(s), "l"(g));
}
#define CP_COMMIT() asm volatile("cp.async.commit_group;" ::: "memory")
#define CP_WAIT(n)  asm volatile("cp.async.wait_group %0;" :: "n"(n) : "memory")

__device__ __forceinline__ uint32_t sw128(uint32_t off) {
    return off ^ ((off >> 3) & 0x70);
}
__device__ __forceinline__ void ldsm4(uint32_t* r, uint32_t addr) {
    asm volatile("ldmatrix.sync.aligned.m8n8.x4.shared.b16 {%0,%1,%2,%3}, [%4];"
                 : "=r"(r[0]), "=r"(r[1]), "=r"(r[2]), "=r"(r[3]) : "r"(addr));
}
__device__ __forceinline__ void mma16832s8(int* d, const uint32_t* a, const uint32_t* b) {
    asm volatile(
        "mma.sync.aligned.m16n8k32.row.col.s32.s8.s8.s32 "
        "{%0,%1,%2,%3}, {%4,%5,%6,%7}, {%8,%9}, {%0,%1,%2,%3};"
        : "+r"(d[0]), "+r"(d[1]), "+r"(d[2]), "+r"(d[3])
        : "r"(a[0]), "r"(a[1]), "r"(a[2]), "r"(a[3]), "r"(b[0]), "r"(b[1]));
}

// saturating s8 pack: d = q0 | q1<<8 | q2<<16 | q3<<24
__device__ __forceinline__ uint32_t pack4s8(int q0, int q1, int q2, int q3) {
    uint32_t t, d;
    asm("cvt.pack.sat.s8.s32.b32 %0, %1, %2, %3;" : "=r"(t) : "r"(q3), "r"(q2), "r"(0));
    asm("cvt.pack.sat.s8.s32.b32 %0, %1, %2, %3;" : "=r"(d) : "r"(q1), "r"(q0), "r"(t));
    return d;
}

// Monotone u32 key for float ordering: larger float -> larger key.
__device__ __forceinline__ uint32_t fkey(float v) {
    const uint32_t b = __float_as_uint(v);
    return (b & 0x80000000u) ? ~b : (b | 0x80000000u);
}

// Monotone packed argmax key: larger value -> larger pack; equal value ->
// smaller index -> larger pack (first-index tie-break).
__device__ __forceinline__ void atom_pack_max(unsigned long long* p, float v, int idx) {
    const unsigned long long pk =
        ((unsigned long long)fkey(v) << 32) | (uint32_t)(0x7FFFFFFFu - idx);
    atomicMax(p, pk);
}

// strip-major flattened tile list helpers
__device__ __forceinline__ void strip_of(int t, int& i, int& d) {
    if (t < 33 * 32) { i = t / 33; d = t - i * 33; }
    else { const int u = t - 33 * 32; i = 32 + u / 32; d = u & 31; }
}
__device__ __forceinline__ int strip_end(int i) {
    return (i < 32) ? (i + 1) * 33 : 33 * 32 + (i - 31) * 32;
}

// ---------------------------------------------------------------------------
// Kernel 0: per-row int8 quantization, warp-per-row, fully coalesced.
// ---------------------------------------------------------------------------
__global__ __launch_bounds__(256) void quant_kernel(const float* __restrict__ x) {
    const int warp = threadIdx.x >> 5;
    const int lane = threadIdx.x & 31;
    const int row  = blockIdx.x * 8 + warp;

    const float4* rp = reinterpret_cast<const float4*>(x + (size_t)row * DIM);
    float4 v[4];
#pragma unroll
    for (int q = 0; q < 4; ++q) v[q] = rp[lane + 32 * q];

    uint32_t mb = 0;
#pragma unroll
    for (int q = 0; q < 4; ++q) {
        mb = max(mb, __float_as_uint(fabsf(v[q].x)));
        mb = max(mb, __float_as_uint(fabsf(v[q].y)));
        mb = max(mb, __float_as_uint(fabsf(v[q].z)));
        mb = max(mb, __float_as_uint(fabsf(v[q].w)));
    }
    const float m   = __uint_as_float(__reduce_max_sync(0xffffffffu, mb));
    const float inv = 127.0f / m;

    uint32_t* out32 = reinterpret_cast<uint32_t*>(g_xq) + row * (DIM / 4);
#pragma unroll
    for (int q = 0; q < 4; ++q)
        out32[lane + 32 * q] =
            pack4s8(__float2int_rn(v[q].x * inv), __float2int_rn(v[q].y * inv),
                    __float2int_rn(v[q].z * inv), __float2int_rn(v[q].w * inv));

    if (lane == 0) {
        g_scale[row] = m * (1.0f / 127.0f);
        g_pack[row]  = 0ull;     // key=0 < any real key
        if (row == 0) g_cnt = 0;
    }
}

// ---------------------------------------------------------------------------
// Kernel 1: symmetric (triangular) int8 mma.sync GEMM + dual-sided argmax.
// 148 CTAs x 256 threads, 2x4 warp grid, 64x32 warp tile, 32KB super-chunk
// pipeline (one wait+sync per 32KB). Launched with PDL: grid-dependency
// sync up front before touching quant outputs.
// ---------------------------------------------------------------------------
__global__ __launch_bounds__(256, 1) void gemm_argmax_kernel() {
    cudaGridDependencySynchronize();   // PDL: quant outputs now visible

    extern __shared__ __align__(128) char smem[];
    const uint32_t sb = smem_u32(smem);

    const int tid  = threadIdx.x;
    const int wid  = tid >> 5;
    const int lane = tid & 31;
    const int wr   = wid >> 2;           // warp row (0-1) -> 64 rows
    const int wc   = wid & 3;            // warp col (0-3) -> 32 cols

    const int t_begin = (int)((long long)blockIdx.x * NTILES / NCTA);
    const int t_end   = (int)((long long)(blockIdx.x + 1) * NTILES / NCTA);

    const uint8_t* xq = g_xq;

    const int a_row_lo = ((lane >> 3) & 1) * 8 + (lane & 7);
    const int a_kext   = (lane >> 4) * 16;
    const int b_row_lo = ((lane >> 4) & 1) * 8 + (lane & 7);
    const int b_kext   = ((lane >> 3) & 1) * 16;

    float* sV = reinterpret_cast<float*>(smem + SMO_B);          // scratch [128][4]
    int*   sI = reinterpret_cast<int*>(smem + SMO_B + 2048);

    int t = t_begin;
    while (t < t_end) {
        int strip, d0;
        strip_of(t, strip, d0);
        const int seg_end = min(t_end, strip_end(strip));
        const int NSUP = (seg_end - t) * 2;   // 2 super-chunks per tile
        const int m0   = strip * BM;

        // per-segment row scales (candidate-side factor for the column fold)
        float srow[8];
#pragma unroll
        for (int mt = 0; mt < 4; ++mt) {
            const int r0 = m0 + wr * 64 + mt * 16 + (lane >> 2);
            srow[mt * 2]     = g_scale[r0];
            srow[mt * 2 + 1] = g_scale[r0 + 8];
        }

        __syncthreads();   // prior segment fully consumed A & B & scratch

        // ---- A strip: 4 chunks of [128 x 128] int8, SW128 (one group)
#pragma unroll
        for (int i = 0; i < 16; ++i) {
            const int u   = i * 256 + tid;       // 0..4095 16B units
            const int kc  = u >> 10;
            const int w   = u & 1023;
            const int row = w >> 3;
            const int c16 = w & 7;
            cp16(sb + SMO_A + kc * CHB16 + sw128(row * 128 + c16 * 16),
                 xq + (size_t)(m0 + row) * DIM + kc * 128 + c16 * 16);
        }
        CP_COMMIT();

        // ---- B prologue: super-chunks 0..2 into super-slots 0..2
#pragma unroll
        for (int p = 0; p < 3; ++p) {
            const int j  = (strip + d0 + (p >> 1)) & (NSTRIP - 1);
            const int n0 = j * BN;
#pragma unroll
            for (int i = 0; i < 8; ++i) {
                const int u   = i * 256 + tid;   // 0..2047 16B units
                const int ch  = u >> 10;
                const int w   = u & 1023;
                const int row = w >> 3;
                const int c16 = w & 7;
                const int kc  = (p & 1) * 2 + ch;
                cp16(sb + SMO_B + p * SUPB + ch * CHB16 + sw128(row * 128 + c16 * 16),
                     xq + (size_t)(n0 + row) * DIM + kc * 128 + c16 * 16);
            }
            CP_COMMIT();
        }
        CP_WAIT(3);          // A landed
        __syncthreads();

        int acc[4][4][4];
#pragma unroll
        for (int mt = 0; mt < 4; ++mt)
#pragma unroll
            for (int nt = 0; nt < 4; ++nt)
#pragma unroll
                for (int k = 0; k < 4; ++k) acc[mt][nt][k] = 0;

        float bestV[8];
        int   bestI[8];
#pragma unroll
        for (int i = 0; i < 8; ++i) { bestV[i] = -3.402823466e38f; bestI[i] = 0; }

        for (int g = 0; g < NSUP; ++g) {
            CP_WAIT(2);
            __syncthreads();

            const int gn = g + 3;
            if (gn < NSUP) {
                const int j  = (strip + d0 + (gn >> 1)) & (NSTRIP - 1);
                const int n0 = j * BN;
                const uint32_t dst = sb + SMO_B + (gn & 3) * SUPB;
#pragma unroll
                for (int i = 0; i < 8; ++i) {
                    const int u   = i * 256 + tid;
                    const int ch  = u >> 10;
                    const int w   = u & 1023;
                    const int row = w >> 3;
                    const int c16 = w & 7;
                    const int kc  = (gn & 1) * 2 + ch;
                    cp16(dst + ch * CHB16 + sw128(row * 128 + c16 * 16),
                         xq + (size_t)(n0 + row) * DIM + kc * 128 + c16 * 16);
                }
            }
            CP_COMMIT();

            // ---- compute 2 chunks of this super-chunk
#pragma unroll
            for (int sub = 0; sub < 2; ++sub) {
                const uint32_t abase = sb + SMO_A + ((g & 1) * 2 + sub) * CHB16;
                const uint32_t bbase = sb + SMO_B + (g & 3) * SUPB + sub * CHB16;
                uint32_t afr[4][4][4];    // [ks][mt][4]
                uint32_t bfr[4][2][4];    // [ks][h][4]
#pragma unroll
                for (int ks = 0; ks < 4; ++ks) {
#pragma unroll
                    for (int mt = 0; mt < 4; ++mt) {
                        const int row = wr * 64 + mt * 16 + a_row_lo;
                        ldsm4(afr[ks][mt], abase + sw128(row * 128 + ks * 32 + a_kext));
                    }
#pragma unroll
                    for (int h2 = 0; h2 < 2; ++h2) {
                        const int row = wc * 32 + h2 * 16 + b_row_lo;
                        ldsm4(bfr[ks][h2], bbase + sw128(row * 128 + ks * 32 + b_kext));
                    }
                }
#pragma unroll
                for (int ks = 0; ks < 4; ++ks)
#pragma unroll
                    for (int mt = 0; mt < 4; ++mt)
#pragma unroll
                        for (int nt = 0; nt < 4; ++nt)
                            mma16832s8(acc[mt][nt], afr[ks][mt],
                                       &bfr[ks][nt >> 1][(nt & 1) * 2]);
            }

            // ---- tile finished (odd super-chunk): dual-sided fold, reset
            if (g & 1) {
                const int d    = d0 + (g >> 1);
                const int j    = (strip + d) & (NSTRIP - 1);
                const int nc0  = j * BN + wc * 32;
                const bool diag = (d == 0);

                float scs[8];
#pragma unroll
                for (int nt = 0; nt < 4; ++nt) {
                    const int c0 = nc0 + nt * 8 + (lane & 3) * 2;
                    scs[nt * 2]     = g_scale[c0];
                    scs[nt * 2 + 1] = g_scale[c0 + 1];
                }

                // row side: v = s_col * dot (missing s_row constant per slot)
#pragma unroll
                for (int mt = 0; mt < 4; ++mt) {
                    const int row0 = m0 + wr * 64 + mt * 16 + (lane >> 2);
                    const int row1 = row0 + 8;
#pragma unroll
                    for (int nt = 0; nt < 4; ++nt) {
                        const int c0 = nc0 + nt * 8 + (lane & 3) * 2;
                        const float v00 = (float)acc[mt][nt][0] * scs[nt * 2];
                        const float v01 = (float)acc[mt][nt][1] * scs[nt * 2 + 1];
                        const float v10 = (float)acc[mt][nt][2] * scs[nt * 2];
                        const float v11 = (float)acc[mt][nt][3] * scs[nt * 2 + 1];
                        const int b0 = mt * 2, b1 = mt * 2 + 1;
                        if (c0 != row0 && v00 > bestV[b0]) { bestV[b0] = v00; bestI[b0] = c0; }
                        if (c0 + 1 != row0 && v01 > bestV[b0]) { bestV[b0] = v01; bestI[b0] = c0 + 1; }
                        if (c0 != row1 && v10 > bestV[b1]) { bestV[b1] = v10; bestI[b1] = c0; }
                        if (c0 + 1 != row1 && v11 > bestV[b1]) { bestV[b1] = v11; bestI[b1] = c0 + 1; }
                    }
                }

                // column side: v = s_row * dot, skipped for diagonal tile.
                // Packed 32-bit (truncated key | 127-localrow) shfl+umax.
                if (!diag) {
                    float cV[8];
                    int   cL[8];   // local row within strip (0..127)
#pragma unroll
                    for (int k = 0; k < 8; ++k) { cV[k] = -3.402823466e38f; cL[k] = 0; }
#pragma unroll
                    for (int mt = 0; mt < 4; ++mt) {
                        const int l0 = wr * 64 + mt * 16 + (lane >> 2);
                        const int l1 = l0 + 8;
                        const float s0 = srow[mt * 2], s1 = srow[mt * 2 + 1];
#pragma unroll
                        for (int nt = 0; nt < 4; ++nt) {
                            const int k0 = nt * 2, k1 = nt * 2 + 1;
                            const float v00 = (float)acc[mt][nt][0] * s0;
                            const float v01 = (float)acc[mt][nt][1] * s0;
                            const float v10 = (float)acc[mt][nt][2] * s1;
                            const float v11 = (float)acc[mt][nt][3] * s1;
                            if (v00 > cV[k0]) { cV[k0] = v00; cL[k0] = l0; }
                            if (v10 > cV[k0]) { cV[k0] = v10; cL[k0] = l1; }
                            if (v01 > cV[k1]) { cV[k1] = v01; cL[k1] = l0; }
                            if (v11 > cV[k1]) { cV[k1] = v11; cL[k1] = l1; }
                        }
                    }
#pragma unroll
                    for (int k = 0; k < 8; ++k) {
                        // packed: truncated monotone key (top 25b) | 127-lrow
                        uint32_t pk = (fkey(cV[k]) & 0xFFFFFF80u)
                                      | (uint32_t)(127 - cL[k]);
#pragma unroll
                        for (int o = 4; o <= 16; o <<= 1)
                            pk = max(pk, __shfl_xor_sync(0xffffffffu, pk, o));
                        if ((lane >> 2) == 0) {
                            const int lrow = 127 - (int)(pk & 0x7F);
                            const int col  = nc0 + (k >> 1) * 8 + (lane & 3) * 2 + (k & 1);
                            const unsigned long long pk64 =
                                ((unsigned long long)(pk & 0xFFFFFF80u) << 32) |
                                (uint32_t)(0x7FFFFFFFu - (m0 + lrow));
                            atomicMax(&g_pack[col], pk64);
                        }
                    }
                }

#pragma unroll
                for (int mt = 0; mt < 4; ++mt)
#pragma unroll
                    for (int nt = 0; nt < 4; ++nt) {
                        acc[mt][nt][0] = 0; acc[mt][nt][1] = 0;
                        acc[mt][nt][2] = 0; acc[mt][nt][3] = 0;
                    }
            }
        }

        // ---- flush row-side bests for this strip segment
        __syncthreads();   // ring quiescent -> reuse as scratch
#pragma unroll
        for (int b = 0; b < 8; ++b) {
            float v = bestV[b];
            int   i = bestI[b];
#pragma unroll
            for (int o = 2; o > 0; o >>= 1) {
                const float ov = __shfl_xor_sync(0xffffffffu, v, o);
                const int   oi = __shfl_xor_sync(0xffffffffu, i, o);
                if (ov > v || (ov == v && oi < i)) { v = ov; i = oi; }
            }
            if ((lane & 3) == 0) {
                const int lrow = wr * 64 + (b >> 1) * 16 + (b & 1) * 8 + (lane >> 2);
                sV[lrow * 4 + wc] = v;
                sI[lrow * 4 + wc] = i;
            }
        }
        __syncthreads();
        if (tid < BM) {
            float v = sV[tid * 4];
            int   i = sI[tid * 4];
#pragma unroll
            for (int q = 1; q < 4; ++q) {
                const float ov = sV[tid * 4 + q];
                const int   oi = sI[tid * 4 + q];
                if (ov > v || (ov == v && oi < i)) { v = ov; i = oi; }
            }
            atom_pack_max(&g_pack[m0 + tid], v, i);
        }

        t = seg_end;
    }
}

// ---------------------------------------------------------------------------
// Kernel 2: rho (exact fp32), warp-per-row + block-level fused loss. PDL.
// ---------------------------------------------------------------------------
__global__ __launch_bounds__(256) void rho_loss_kernel(const float* __restrict__ x,
                                                       float* __restrict__ out) {
    cudaGridDependencySynchronize();   // PDL: gemm outputs now visible

    const int warp = threadIdx.x >> 5;
    const int lane = threadIdx.x & 31;
    const int row  = blockIdx.x * 8 + warp;

    const unsigned long long p = g_pack[row];
    const int nn = 0x7FFFFFFF - (int)(uint32_t)(p & 0xFFFFFFFFull);

    const float4* ra = reinterpret_cast<const float4*>(x + (size_t)row * DIM);
    const float4* rb = reinterpret_cast<const float4*>(x + (size_t)nn  * DIM);
    float s = 0.0f;
#pragma unroll
    for (int q = 0; q < 4; ++q) {
        const float4 a = ra[lane + 32 * q];
        const float4 b = rb[lane + 32 * q];
        const float dx = a.x - b.x + 1e-6f;
        const float dy = a.y - b.y + 1e-6f;
        const float dz = a.z - b.z + 1e-6f;
        const float dw = a.w - b.w + 1e-6f;
        s += dx * dx + dy * dy + dz * dz + dw * dw;
    }
#pragma unroll
    for (int o = 16; o > 0; o >>= 1) s += __shfl_xor_sync(0xffffffffu, s, o);

    if (lane == 0) g_term[row] = logf(sqrtf(s) + 1e-8f);

    __shared__ int slast;
    __shared__ float ws[8];
    __threadfence();
    __syncthreads();
    if (threadIdx.x == 0) {
        const int old = atomicAdd(&g_cnt, 8);
        slast = (old == NROW - 8);
    }
    __syncthreads();

    if (slast) {   // last block: deterministic fixed-order global reduction
        __threadfence();
        float acc = 0.0f;
        for (int i = threadIdx.x; i < NROW; i += 256) acc += g_term[i];
#pragma unroll
        for (int o = 16; o > 0; o >>= 1) acc += __shfl_xor_sync(0xffffffffu, acc, o);
        if (lane == 0) ws[warp] = acc;
        __syncthreads();
        if (threadIdx.x == 0) {
            float tot = 0.0f;
#pragma unroll
            for (int w = 0; w < 8; ++w) tot += ws[w];
            out[0] = -tot / (float)NROW;
        }
    }
}

extern "C" void kernel_launch(void* const* d_in, const int* in_sizes, int n_in,
                              void* d_out, int out_size) {
    (void)in_sizes; (void)n_in; (void)out_size;
    const float* x = (const float*)d_in[0];
    float* out = (float*)d_out;

    cudaFuncSetAttribute(gemm_argmax_kernel,
                         cudaFuncAttributeMaxDynamicSharedMemorySize, SMEM_SZ);

    quant_kernel<<<NROW / 8, 256>>>(x);

    // PDL launches: dependent kernels go resident early; their leading
    // cudaGridDependencySynchronize() enforces ordering.
    cudaLaunchAttribute attr[1];
    attr[0].id = cudaLaunchAttributeProgrammaticStreamSerialization;
    attr[0].val.programmaticStreamSerializationAllowed = 1;

    {
        cudaLaunchConfig_t cfg = {};
        cfg.gridDim  = dim3(NCTA, 1, 1);
        cfg.blockDim = dim3(256, 1, 1);
        cfg.dynamicSmemBytes = SMEM_SZ;
        cfg.attrs    = attr;
        cfg.numAttrs = 1;
        cudaLaunchKernelEx(&cfg, gemm_argmax_kernel);
    }
    {
        cudaLaunchConfig_t cfg = {};
        cfg.gridDim  = dim3(NROW / 8, 1, 1);
        cfg.blockDim = dim3(256, 1, 1);
        cfg.dynamicSmemBytes = 0;
        cfg.attrs    = attr;
        cfg.numAttrs = 1;
        cudaLaunchKernelEx(&cfg, rho_loss_kernel, x, out);
    }
}

// round 17
// speedup vs baseline: 1.2312x; 1.0004x over previous
#include <cuda_runtime.h>
#include <math.h>
#include <stdint.h>

// ---------------------------------------------------------------------------
// Problem constants (x: [8192, 512] fp32)
// ---------------------------------------------------------------------------
constexpr int NROW = 8192;
constexpr int DIM  = 512;

constexpr int BM   = 128;           // rows per strip
constexpr int BN   = 128;           // cols per tile
constexpr int NSTRIP = NROW / BM;   // 64 strips
constexpr int CHB16 = BM * 128;     // 16384 B per 16KB chunk (K=128 int8)
constexpr int SUPB  = 2 * CHB16;    // 32768 B super-chunk (K=256)
constexpr int NTILES = 33 * 32 + 32 * 32;   // 2080
constexpr int NCTA   = 148;

constexpr int SMO_A = 0;                       // 4 * 16KB resident A strip
constexpr int SMO_B = 4 * CHB16;               // 4-slot super ring (4 * 32KB)
constexpr int SMEM_SZ = SMO_B + 4 * SUPB;      // 196608 B

// Scratch (no allocations allowed anywhere)
__device__ uint8_t g_xq[NROW * DIM];           // int8 quantized x
__device__ float   g_scale[NROW];              // per-row dequant scale
__device__ unsigned long long g_pack[NROW];    // packed (valkey<<32)|(0x7FFFFFFF-idx)
__device__ float g_term[NROW];
__device__ int   g_cnt;

// ---------------------------------------------------------------------------
// PTX helpers (compute_100-safe: cp.async / ldmatrix / mma.sync / redux)
// ---------------------------------------------------------------------------
__device__ __forceinline__ uint32_t smem_u32(const void* p) {
    uint32_t a;
    asm("{ .reg .u64 t; cvta.to.shared.u64 t, %1; cvt.u32.u64 %0, t; }"
        : "=r"(a) : "l"(p));
    return a;
}
__device__ __forceinline__ void cp16(uint32_t s, const void* g) {
    asm volatile("cp.async.cg.shared.global [%0], [%1], 16;" :: "r"(s), "l"(g));
}
#define CP_COMMIT() asm volatile("cp.async.commit_group;" ::: "memory")
#define CP_WAIT(n)  asm volatile("cp.async.wait_group %0;" :: "n"(n) : "memory")

__device__ __forceinline__ uint32_t sw128(uint32_t off) {
    return off ^ ((off >> 3) & 0x70);
}
__device__ __forceinline__ void ldsm4(uint32_t* r, uint32_t addr) {
    asm volatile("ldmatrix.sync.aligned.m8n8.x4.shared.b16 {%0,%1,%2,%3}, [%4];"
                 : "=r"(r[0]), "=r"(r[1]), "=r"(r[2]), "=r"(r[3]) : "r"(addr));
}
__device__ __forceinline__ void mma16832s8(int* d, const uint32_t* a, const uint32_t* b) {
    asm volatile(
        "mma.sync.aligned.m16n8k32.row.col.s32.s8.s8.s32 "
        "{%0,%1,%2,%3}, {%4,%5,%6,%7}, {%8,%9}, {%0,%1,%2,%3};"
        : "+r"(d[0]), "+r"(d[1]), "+r"(d[2]), "+r"(d[3])
        : "r"(a[0]), "r"(a[1]), "r"(a[2]), "r"(a[3]), "r"(b[0]), "r"(b[1]));
}

// saturating s8 pack: d = q0 | q1<<8 | q2<<16 | q3<<24
__device__ __forceinline__ uint32_t pack4s8(int q0, int q1, int q2, int q3) {
    uint32_t t, d;
    asm("cvt.pack.sat.s8.s32.b32 %0, %1, %2, %3;" : "=r"(t) : "r"(q3), "r"(q2), "r"(0));
    asm("cvt.pack.sat.s8.s32.b32 %0, %1, %2, %3;" : "=r"(d) : "r"(q1), "r"(q0), "r"(t));
    return d;
}

// Monotone u32 key for float ordering: larger float -> larger key.
__device__ __forceinline__ uint32_t fkey(float v) {
    const uint32_t b = __float_as_uint(v);
    return (b & 0x80000000u) ? ~b : (b | 0x80000000u);
}

// Monotone packed argmax key: larger value -> larger pack; equal value ->
// smaller index -> larger pack (first-index tie-break).
__device__ __forceinline__ void atom_pack_max(unsigned long long* p, float v, int idx) {
    const unsigned long long pk =
        ((unsigned long long)fkey(v) << 32) | (uint32_t)(0x7FFFFFFFu - idx);
    atomicMax(p, pk);
}

// strip-major flattened tile list helpers
__device__ __forceinline__ void strip_of(int t, int& i, int& d) {
    if (t < 33 * 32) { i = t / 33; d = t - i * 33; }
    else { const int u = t - 33 * 32; i = 32 + u / 32; d = u & 31; }
}
__device__ __forceinline__ int strip_end(int i) {
    return (i < 32) ? (i + 1) * 33 : 33 * 32 + (i - 31) * 32;
}

// ---------------------------------------------------------------------------
// Kernel 0: per-row int8 quantization, warp-per-row, fully coalesced.
// ---------------------------------------------------------------------------
__global__ __launch_bounds__(256) void quant_kernel(const float* __restrict__ x) {
    const int warp = threadIdx.x >> 5;
    const int lane = threadIdx.x & 31;
    const int row  = blockIdx.x * 8 + warp;

    const float4* rp = reinterpret_cast<const float4*>(x + (size_t)row * DIM);
    float4 v[4];
#pragma unroll
    for (int q = 0; q < 4; ++q) v[q] = rp[lane + 32 * q];

    uint32_t mb = 0;
#pragma unroll
    for (int q = 0; q < 4; ++q) {
        mb = max(mb, __float_as_uint(fabsf(v[q].x)));
        mb = max(mb, __float_as_uint(fabsf(v[q].y)));
        mb = max(mb, __float_as_uint(fabsf(v[q].z)));
        mb = max(mb, __float_as_uint(fabsf(v[q].w)));
    }
    const float m   = __uint_as_float(__reduce_max_sync(0xffffffffu, mb));
    const float inv = 127.0f / m;

    uint32_t* out32 = reinterpret_cast<uint32_t*>(g_xq) + row * (DIM / 4);
#pragma unroll
    for (int q = 0; q < 4; ++q)
        out32[lane + 32 * q] =
            pack4s8(__float2int_rn(v[q].x * inv), __float2int_rn(v[q].y * inv),
                    __float2int_rn(v[q].z * inv), __float2int_rn(v[q].w * inv));

    if (lane == 0) {
        g_scale[row] = m * (1.0f / 127.0f);
        g_pack[row]  = 0ull;     // key=0 < any real key
        if (row == 0) g_cnt = 0;
    }
}

// ---------------------------------------------------------------------------
// Kernel 1: symmetric (triangular) int8 mma.sync GEMM + dual-sided argmax.
// 148 CTAs x 256 threads, 2x4 warp grid, 64x32 warp tile, 32KB super-chunk
// pipeline. PDL: scheduling arithmetic hoisted before the grid-dependency
// sync; everything touching quant outputs stays after it.
// ---------------------------------------------------------------------------
__global__ __launch_bounds__(256, 1) void gemm_argmax_kernel() {
    extern __shared__ __align__(128) char smem[];
    const uint32_t sb = smem_u32(smem);

    const int tid  = threadIdx.x;
    const int wid  = tid >> 5;
    const int lane = tid & 31;
    const int wr   = wid >> 2;           // warp row (0-1) -> 64 rows
    const int wc   = wid & 3;            // warp col (0-3) -> 32 cols

    const int t_begin = (int)((long long)blockIdx.x * NTILES / NCTA);
    const int t_end   = (int)((long long)(blockIdx.x + 1) * NTILES / NCTA);

    const int a_row_lo = ((lane >> 3) & 1) * 8 + (lane & 7);
    const int a_kext   = (lane >> 4) * 16;
    const int b_row_lo = ((lane >> 4) & 1) * 8 + (lane & 7);
    const int b_kext   = ((lane >> 3) & 1) * 16;

    float* sV = reinterpret_cast<float*>(smem + SMO_B);          // scratch [128][4]
    int*   sI = reinterpret_cast<int*>(smem + SMO_B + 2048);

    cudaGridDependencySynchronize();   // PDL: quant outputs now visible
    const uint8_t* xq = g_xq;

    int t = t_begin;
    while (t < t_end) {
        int strip, d0;
        strip_of(t, strip, d0);
        const int seg_end = min(t_end, strip_end(strip));
        const int NSUP = (seg_end - t) * 2;   // 2 super-chunks per tile
        const int m0   = strip * BM;

        // per-segment row scales (candidate-side factor for the column fold)
        float srow[8];
#pragma unroll
        for (int mt = 0; mt < 4; ++mt) {
            const int r0 = m0 + wr * 64 + mt * 16 + (lane >> 2);
            srow[mt * 2]     = g_scale[r0];
            srow[mt * 2 + 1] = g_scale[r0 + 8];
        }

        __syncthreads();   // prior segment fully consumed A & B & scratch

        // ---- A strip: 4 chunks of [128 x 128] int8, SW128 (one group)
#pragma unroll
        for (int i = 0; i < 16; ++i) {
            const int u   = i * 256 + tid;       // 0..4095 16B units
            const int kc  = u >> 10;
            const int w   = u & 1023;
            const int row = w >> 3;
            const int c16 = w & 7;
            cp16(sb + SMO_A + kc * CHB16 + sw128(row * 128 + c16 * 16),
                 xq + (size_t)(m0 + row) * DIM + kc * 128 + c16 * 16);
        }
        CP_COMMIT();

        // ---- B prologue: super-chunks 0..2 into super-slots 0..2
#pragma unroll
        for (int p = 0; p < 3; ++p) {
            const int j  = (strip + d0 + (p >> 1)) & (NSTRIP - 1);
            const int n0 = j * BN;
#pragma unroll
            for (int i = 0; i < 8; ++i) {
                const int u   = i * 256 + tid;   // 0..2047 16B units
                const int ch  = u >> 10;
                const int w   = u & 1023;
                const int row = w >> 3;
                const int c16 = w & 7;
                const int kc  = (p & 1) * 2 + ch;
                cp16(sb + SMO_B + p * SUPB + ch * CHB16 + sw128(row * 128 + c16 * 16),
                     xq + (size_t)(n0 + row) * DIM + kc * 128 + c16 * 16);
            }
            CP_COMMIT();
        }
        CP_WAIT(3);          // A landed
        __syncthreads();

        int acc[4][4][4];
#pragma unroll
        for (int mt = 0; mt < 4; ++mt)
#pragma unroll
            for (int nt = 0; nt < 4; ++nt)
#pragma unroll
                for (int k = 0; k < 4; ++k) acc[mt][nt][k] = 0;

        float bestV[8];
        int   bestI[8];
#pragma unroll
        for (int i = 0; i < 8; ++i) { bestV[i] = -3.402823466e38f; bestI[i] = 0; }

        for (int g = 0; g < NSUP; ++g) {
            CP_WAIT(2);
            __syncthreads();

            const int gn = g + 3;
            if (gn < NSUP) {
                const int j  = (strip + d0 + (gn >> 1)) & (NSTRIP - 1);
                const int n0 = j * BN;
                const uint32_t dst = sb + SMO_B + (gn & 3) * SUPB;
#pragma unroll
                for (int i = 0; i < 8; ++i) {
                    const int u   = i * 256 + tid;
                    const int ch  = u >> 10;
                    const int w   = u & 1023;
                    const int row = w >> 3;
                    const int c16 = w & 7;
                    const int kc  = (gn & 1) * 2 + ch;
                    cp16(dst + ch * CHB16 + sw128(row * 128 + c16 * 16),
                         xq + (size_t)(n0 + row) * DIM + kc * 128 + c16 * 16);
                }
            }
            CP_COMMIT();

            // ---- compute 2 chunks of this super-chunk
#pragma unroll
            for (int sub = 0; sub < 2; ++sub) {
                const uint32_t abase = sb + SMO_A + ((g & 1) * 2 + sub) * CHB16;
                const uint32_t bbase = sb + SMO_B + (g & 3) * SUPB + sub * CHB16;
                uint32_t afr[4][4][4];    // [ks][mt][4]
                uint32_t bfr[4][2][4];    // [ks][h][4]
#pragma unroll
                for (int ks = 0; ks < 4; ++ks) {
#pragma unroll
                    for (int mt = 0; mt < 4; ++mt) {
                        const int row = wr * 64 + mt * 16 + a_row_lo;
                        ldsm4(afr[ks][mt], abase + sw128(row * 128 + ks * 32 + a_kext));
                    }
#pragma unroll
                    for (int h2 = 0; h2 < 2; ++h2) {
                        const int row = wc * 32 + h2 * 16 + b_row_lo;
                        ldsm4(bfr[ks][h2], bbase + sw128(row * 128 + ks * 32 + b_kext));
                    }
                }
#pragma unroll
                for (int ks = 0; ks < 4; ++ks)
#pragma unroll
                    for (int mt = 0; mt < 4; ++mt)
#pragma unroll
                        for (int nt = 0; nt < 4; ++nt)
                            mma16832s8(acc[mt][nt], afr[ks][mt],
                                       &bfr[ks][nt >> 1][(nt & 1) * 2]);
            }

            // ---- tile finished (odd super-chunk): dual-sided fold, reset
            if (g & 1) {
                const int d    = d0 + (g >> 1);
                const int j    = (strip + d) & (NSTRIP - 1);
                const int nc0  = j * BN + wc * 32;
                const bool diag = (d == 0);

                float scs[8];
#pragma unroll
                for (int nt = 0; nt < 4; ++nt) {
                    const int c0 = nc0 + nt * 8 + (lane & 3) * 2;
                    scs[nt * 2]     = g_scale[c0];
                    scs[nt * 2 + 1] = g_scale[c0 + 1];
                }

                // row side: v = s_col * dot (missing s_row constant per slot)
#pragma unroll
                for (int mt = 0; mt < 4; ++mt) {
                    const int row0 = m0 + wr * 64 + mt * 16 + (lane >> 2);
                    const int row1 = row0 + 8;
#pragma unroll
                    for (int nt = 0; nt < 4; ++nt) {
                        const int c0 = nc0 + nt * 8 + (lane & 3) * 2;
                        const float v00 = (float)acc[mt][nt][0] * scs[nt * 2];
                        const float v01 = (float)acc[mt][nt][1] * scs[nt * 2 + 1];
                        const float v10 = (float)acc[mt][nt][2] * scs[nt * 2];
                        const float v11 = (float)acc[mt][nt][3] * scs[nt * 2 + 1];
                        const int b0 = mt * 2, b1 = mt * 2 + 1;
                        if (c0 != row0 && v00 > bestV[b0]) { bestV[b0] = v00; bestI[b0] = c0; }
                        if (c0 + 1 != row0 && v01 > bestV[b0]) { bestV[b0] = v01; bestI[b0] = c0 + 1; }
                        if (c0 != row1 && v10 > bestV[b1]) { bestV[b1] = v10; bestI[b1] = c0; }
                        if (c0 + 1 != row1 && v11 > bestV[b1]) { bestV[b1] = v11; bestI[b1] = c0 + 1; }
                    }
                }

                // column side: v = s_row * dot, skipped for diagonal tile.
                // Packed 32-bit (truncated key | 127-localrow) shfl+umax.
                if (!diag) {
                    float cV[8];
                    int   cL[8];   // local row within strip (0..127)
#pragma unroll
                    for (int k = 0; k < 8; ++k) { cV[k] = -3.402823466e38f; cL[k] = 0; }
#pragma unroll
                    for (int mt = 0; mt < 4; ++mt) {
                        const int l0 = wr * 64 + mt * 16 + (lane >> 2);
                        const int l1 = l0 + 8;
                        const float s0 = srow[mt * 2], s1 = srow[mt * 2 + 1];
#pragma unroll
                        for (int nt = 0; nt < 4; ++nt) {
                            const int k0 = nt * 2, k1 = nt * 2 + 1;
                            const float v00 = (float)acc[mt][nt][0] * s0;
                            const float v01 = (float)acc[mt][nt][1] * s0;
                            const float v10 = (float)acc[mt][nt][2] * s1;
                            const float v11 = (float)acc[mt][nt][3] * s1;
                            if (v00 > cV[k0]) { cV[k0] = v00; cL[k0] = l0; }
                            if (v10 > cV[k0]) { cV[k0] = v10; cL[k0] = l1; }
                            if (v01 > cV[k1]) { cV[k1] = v01; cL[k1] = l0; }
                            if (v11 > cV[k1]) { cV[k1] = v11; cL[k1] = l1; }
                        }
                    }
#pragma unroll
                    for (int k = 0; k < 8; ++k) {
                        // packed: truncated monotone key (top 25b) | 127-lrow
                        uint32_t pk = (fkey(cV[k]) & 0xFFFFFF80u)
                                      | (uint32_t)(127 - cL[k]);
#pragma unroll
                        for (int o = 4; o <= 16; o <<= 1)
                            pk = max(pk, __shfl_xor_sync(0xffffffffu, pk, o));
                        if ((lane >> 2) == 0) {
                            const int lrow = 127 - (int)(pk & 0x7F);
                            const int col  = nc0 + (k >> 1) * 8 + (lane & 3) * 2 + (k & 1);
                            const unsigned long long pk64 =
                                ((unsigned long long)(pk & 0xFFFFFF80u) << 32) |
                                (uint32_t)(0x7FFFFFFFu - (m0 + lrow));
                            atomicMax(&g_pack[col], pk64);
                        }
                    }
                }

#pragma unroll
                for (int mt = 0; mt < 4; ++mt)
#pragma unroll
                    for (int nt = 0; nt < 4; ++nt) {
                        acc[mt][nt][0] = 0; acc[mt][nt][1] = 0;
                        acc[mt][nt][2] = 0; acc[mt][nt][3] = 0;
                    }
            }
        }

        // ---- flush row-side bests for this strip segment
        __syncthreads();   // ring quiescent -> reuse as scratch
#pragma unroll
        for (int b = 0; b < 8; ++b) {
            float v = bestV[b];
            int   i = bestI[b];
#pragma unroll
            for (int o = 2; o > 0; o >>= 1) {
                const float ov = __shfl_xor_sync(0xffffffffu, v, o);
                const int   oi = __shfl_xor_sync(0xffffffffu, i, o);
                if (ov > v || (ov == v && oi < i)) { v = ov; i = oi; }
            }
            if ((lane & 3) == 0) {
                const int lrow = wr * 64 + (b >> 1) * 16 + (b & 1) * 8 + (lane >> 2);
                sV[lrow * 4 + wc] = v;
                sI[lrow * 4 + wc] = i;
            }
        }
        __syncthreads();
        if (tid < BM) {
            float v = sV[tid * 4];
            int   i = sI[tid * 4];
#pragma unroll
            for (int q = 1; q < 4; ++q) {
                const float ov = sV[tid * 4 + q];
                const int   oi = sI[tid * 4 + q];
                if (ov > v || (ov == v && oi < i)) { v = ov; i = oi; }
            }
            atom_pack_max(&g_pack[m0 + tid], v, i);
        }

        t = seg_end;
    }
}

// ---------------------------------------------------------------------------
// Kernel 2: rho (exact fp32), warp-per-row + block-level fused loss. PDL:
// the ra = x[row] loads (input-only, no dependency on gemm) are issued
// BEFORE the grid-dependency sync, overlapping the gemm's imbalanced tail.
// ---------------------------------------------------------------------------
__global__ __launch_bounds__(256) void rho_loss_kernel(const float* __restrict__ x,
                                                       float* __restrict__ out) {
    const int warp = threadIdx.x >> 5;
    const int lane = threadIdx.x & 31;
    const int row  = blockIdx.x * 8 + warp;

    // Pre-sync: x is input-only; safe to read before the gemm completes.
    const float4* ra = reinterpret_cast<const float4*>(x + (size_t)row * DIM);
    float4 a[4];
#pragma unroll
    for (int q = 0; q < 4; ++q) a[q] = ra[lane + 32 * q];

    cudaGridDependencySynchronize();   // PDL: g_pack now visible

    const unsigned long long p = g_pack[row];
    const int nn = 0x7FFFFFFF - (int)(uint32_t)(p & 0xFFFFFFFFull);

    const float4* rb = reinterpret_cast<const float4*>(x + (size_t)nn * DIM);
    float s = 0.0f;
#pragma unroll
    for (int q = 0; q < 4; ++q) {
        const float4 b = rb[lane + 32 * q];
        const float dx = a[q].x - b.x + 1e-6f;
        const float dy = a[q].y - b.y + 1e-6f;
        const float dz = a[q].z - b.z + 1e-6f;
        const float dw = a[q].w - b.w + 1e-6f;
        s += dx * dx + dy * dy + dz * dz + dw * dw;
    }
#pragma unroll
    for (int o = 16; o > 0; o >>= 1) s += __shfl_xor_sync(0xffffffffu, s, o);

    if (lane == 0) g_term[row] = logf(sqrtf(s) + 1e-8f);

    __shared__ int slast;
    __shared__ float ws[8];
    __threadfence();
    __syncthreads();
    if (threadIdx.x == 0) {
        const int old = atomicAdd(&g_cnt, 8);
        slast = (old == NROW - 8);
    }
    __syncthreads();

    if (slast) {   // last block: deterministic fixed-order global reduction
        __threadfence();
        float acc = 0.0f;
        for (int i = threadIdx.x; i < NROW; i += 256) acc += g_term[i];
#pragma unroll
        for (int o = 16; o > 0; o >>= 1) acc += __shfl_xor_sync(0xffffffffu, acc, o);
        if (lane == 0) ws[warp] = acc;
        __syncthreads();
        if (threadIdx.x == 0) {
            float tot = 0.0f;
#pragma unroll
            for (int w = 0; w < 8; ++w) tot += ws[w];
            out[0] = -tot / (float)NROW;
        }
    }
}

extern "C" void kernel_launch(void* const* d_in, const int* in_sizes, int n_in,
                              void* d_out, int out_size) {
    (void)in_sizes; (void)n_in; (void)out_size;
    const float* x = (const float*)d_in[0];
    float* out = (float*)d_out;

    cudaFuncSetAttribute(gemm_argmax_kernel,
                         cudaFuncAttributeMaxDynamicSharedMemorySize, SMEM_SZ);

    quant_kernel<<<NROW / 8, 256>>>(x);

    cudaLaunchAttribute attr[1];
    attr[0].id = cudaLaunchAttributeProgrammaticStreamSerialization;
    attr[0].val.programmaticStreamSerializationAllowed = 1;

    {
        cudaLaunchConfig_t cfg = {};
        cfg.gridDim  = dim3(NCTA, 1, 1);
        cfg.blockDim = dim3(256, 1, 1);
        cfg.dynamicSmemBytes = SMEM_SZ;
        cfg.attrs    = attr;
        cfg.numAttrs = 1;
        cudaLaunchKernelEx(&cfg, gemm_argmax_kernel);
    }
    {
        cudaLaunchConfig_t cfg = {};
        cfg.gridDim  = dim3(NROW / 8, 1, 1);
        cfg.blockDim = dim3(256, 1, 1);
        cfg.dynamicSmemBytes = 0;
        cfg.attrs    = attr;
        cfg.numAttrs = 1;
        cudaLaunchKernelEx(&cfg, rho_loss_kernel, x, out);
    }
}